// round 1
// baseline (speedup 1.0000x reference)
#include <cuda_runtime.h>
#include <math.h>

#define BB 8
#define TT 1024
#define EE 128
#define HH 8
#define TS (HH*EE)   // 1024 floats per token row

// Scratch (allocation-free): 4 x 32MB fp32
__device__ float g_q[BB*TT*HH*EE];
__device__ float g_k[BB*TT*HH*EE];
__device__ float g_v[BB*TT*HH*EE];
__device__ float g_o[BB*TT*HH*EE];

// ---------------------------------------------------------------------------
// C[M,N] = A[M,K] @ W[N,K]^T (+ bias). BM=128, BN=64, BK=16, 256 thr, 8x4 tile
// ---------------------------------------------------------------------------
__global__ __launch_bounds__(256) void sgemm_nt(
    const float* __restrict__ A, const float* __restrict__ W,
    float* __restrict__ C, const float* __restrict__ bias,
    int M, int N, int K)
{
    __shared__ float As[16][128];
    __shared__ float Bs[16][64];
    const int tid = threadIdx.x;
    const int tx = tid & 15;         // 16 cols of threads  -> 64 N
    const int ty = tid >> 4;         // 16 rows of threads  -> 128 M
    const int bm = blockIdx.x * 128;
    const int bn = blockIdx.y * 64;

    float acc[8][4];
#pragma unroll
    for (int i = 0; i < 8; i++)
#pragma unroll
        for (int j = 0; j < 4; j++) acc[i][j] = 0.f;

    const int lr = tid >> 2;          // 0..63
    const int lc = (tid & 3) << 2;    // 0,4,8,12

    for (int k0 = 0; k0 < K; k0 += 16) {
        float4 a0 = *(const float4*)&A[(bm + lr) * K + k0 + lc];
        float4 a1 = *(const float4*)&A[(bm + 64 + lr) * K + k0 + lc];
        float4 b0 = *(const float4*)&W[(bn + lr) * K + k0 + lc];
        __syncthreads();
        As[lc+0][lr] = a0.x; As[lc+1][lr] = a0.y; As[lc+2][lr] = a0.z; As[lc+3][lr] = a0.w;
        As[lc+0][64+lr] = a1.x; As[lc+1][64+lr] = a1.y; As[lc+2][64+lr] = a1.z; As[lc+3][64+lr] = a1.w;
        Bs[lc+0][lr] = b0.x; Bs[lc+1][lr] = b0.y; Bs[lc+2][lr] = b0.z; Bs[lc+3][lr] = b0.w;
        __syncthreads();
#pragma unroll
        for (int k = 0; k < 16; k++) {
            float4 af0 = *(const float4*)&As[k][ty*8];
            float4 af1 = *(const float4*)&As[k][ty*8 + 4];
            float4 bf  = *(const float4*)&Bs[k][tx*4];
            float av[8] = {af0.x, af0.y, af0.z, af0.w, af1.x, af1.y, af1.z, af1.w};
            float bv[4] = {bf.x, bf.y, bf.z, bf.w};
#pragma unroll
            for (int i = 0; i < 8; i++)
#pragma unroll
                for (int j = 0; j < 4; j++)
                    acc[i][j] += av[i] * bv[j];
        }
    }

#pragma unroll
    for (int i = 0; i < 8; i++) {
        int row = bm + ty*8 + i;
        float4 o;
        o.x = acc[i][0]; o.y = acc[i][1]; o.z = acc[i][2]; o.w = acc[i][3];
        if (bias) {
            o.x += bias[bn + tx*4 + 0];
            o.y += bias[bn + tx*4 + 1];
            o.z += bias[bn + tx*4 + 2];
            o.w += bias[bn + tx*4 + 3];
        }
        *(float4*)&C[row * N + bn + tx*4] = o;
    }
}

// ---------------------------------------------------------------------------
// Flash-style attention, fp32. Block = (q-tile of 64, head, batch). 256 thr.
// Online softmax with exact reference mask semantics:
//   causal (k>q) -> -1e30 (stands in for -inf), then mask==0 -> -1e9 overwrite.
// If any row in the tile still has max <= -1e8 after the causal tiles (its
// whole causal prefix was padding-masked), extend the loop over ALL key
// tiles: the -1e9 future entries then participate exactly as in the reference.
// ---------------------------------------------------------------------------
__global__ __launch_bounds__(256) void attn_kernel(const int* __restrict__ mask)
{
    extern __shared__ float sm[];
    float* Qs  = sm;                 // [128][64]  (d-major, transposed)
    float* Ks  = Qs + 128*64;        // [128][64]
    float* Vs  = Ks + 128*64;        // [64][128]
    float* Ps  = Vs + 64*128;        // [64][65]   Ps[key*65 + row]
    float* m_s = Ps + 64*65;         // [64]
    float* l_s = m_s + 64;           // [64]
    float* c_s = l_s + 64;           // [64]

    const int qt  = blockIdx.x;      // 0..15
    const int h   = blockIdx.y;
    const int b   = blockIdx.z;
    const int tid = threadIdx.x;
    const int tx  = tid & 15, ty  = tid >> 4;   // GEMM1 layout (4x4)
    const int tx2 = tid & 31, ty2 = tid >> 5;   // GEMM2 layout (8 rows x 4 cols)

    const float* qg = g_q + (b*TT)*TS + h*EE;
    const float* kg = g_k + (b*TT)*TS + h*EE;
    const float* vg = g_v + (b*TT)*TS + h*EE;

    // Load Q tile transposed: Qs[d][r]
#pragma unroll
    for (int it = 0; it < 8; it++) {
        int idx = tid + it*256;          // 0..2047 float4 slots (64 rows x 32)
        int r   = idx >> 5;
        int d4  = (idx & 31) << 2;
        float4 v = *(const float4*)&qg[(qt*64 + r)*TS + d4];
        Qs[(d4+0)*64 + r] = v.x; Qs[(d4+1)*64 + r] = v.y;
        Qs[(d4+2)*64 + r] = v.z; Qs[(d4+3)*64 + r] = v.w;
    }
    if (tid < 64) { m_s[tid] = -1e30f; l_s[tid] = 0.f; c_s[tid] = 1.f; }

    float acc[8][4];
#pragma unroll
    for (int i = 0; i < 8; i++)
#pragma unroll
        for (int j = 0; j < 4; j++) acc[i][j] = 0.f;

    int  kt_end   = qt;
    bool extended = false;
    for (int kt = 0; kt <= kt_end; kt++) {
        __syncthreads();   // prior GEMM2 finished before overwriting tiles
        // Load K (transposed) and V (natural) tiles
#pragma unroll
        for (int it = 0; it < 8; it++) {
            int idx = tid + it*256;
            int r   = idx >> 5;
            int d4  = (idx & 31) << 2;
            float4 kv = *(const float4*)&kg[(kt*64 + r)*TS + d4];
            Ks[(d4+0)*64 + r] = kv.x; Ks[(d4+1)*64 + r] = kv.y;
            Ks[(d4+2)*64 + r] = kv.z; Ks[(d4+3)*64 + r] = kv.w;
            float4 vv = *(const float4*)&vg[(kt*64 + r)*TS + d4];
            *(float4*)&Vs[r*128 + d4] = vv;
        }
        __syncthreads();

        // GEMM1: S[64][64] fragments (4x4/thread)
        float s[4][4] = {};
#pragma unroll 16
        for (int d = 0; d < 128; d++) {
            float4 a  = *(const float4*)&Qs[d*64 + ty*4];
            float4 kk = *(const float4*)&Ks[d*64 + tx*4];
            float av[4] = {a.x, a.y, a.z, a.w};
            float bv[4] = {kk.x, kk.y, kk.z, kk.w};
#pragma unroll
            for (int i = 0; i < 4; i++)
#pragma unroll
                for (int j = 0; j < 4; j++)
                    s[i][j] += av[i] * bv[j];
        }

        const float scale = 0.0883883476483184f;   // 1/sqrt(128)
        const int q0 = qt*64 + ty*4;
        const int k0 = kt*64 + tx*4;
#pragma unroll
        for (int i = 0; i < 4; i++) {
            const int q = q0 + i;
            const int r = ty*4 + i;
            float rm = -3e38f;
#pragma unroll
            for (int j = 0; j < 4; j++) {
                int kk = k0 + j;
                float v = s[i][j] * scale;
                if (kk > q) v = -1e30f;                 // causal first
                if (mask[q*TT + kk] == 0) v = -1e9f;    // padding overwrites
                s[i][j] = v;
                rm = fmaxf(rm, v);
            }
            // row-max across the 16 threads owning this row
            rm = fmaxf(rm, __shfl_xor_sync(0xffffffffu, rm, 1));
            rm = fmaxf(rm, __shfl_xor_sync(0xffffffffu, rm, 2));
            rm = fmaxf(rm, __shfl_xor_sync(0xffffffffu, rm, 4));
            rm = fmaxf(rm, __shfl_xor_sync(0xffffffffu, rm, 8));
            float mo = m_s[r];
            float mn = fmaxf(mo, rm);
            float rsum = 0.f;
#pragma unroll
            for (int j = 0; j < 4; j++) {
                float p = __expf(s[i][j] - mn);
                s[i][j] = p;
                rsum += p;
            }
            rsum += __shfl_xor_sync(0xffffffffu, rsum, 1);
            rsum += __shfl_xor_sync(0xffffffffu, rsum, 2);
            rsum += __shfl_xor_sync(0xffffffffu, rsum, 4);
            rsum += __shfl_xor_sync(0xffffffffu, rsum, 8);
            float corr = __expf(mo - mn);
            __syncwarp();   // all 16 read m_s/l_s state before owner updates
            if (tx == 0) {
                m_s[r] = mn;
                l_s[r] = l_s[r] * corr + rsum;
                c_s[r] = corr;
            }
#pragma unroll
            for (int j = 0; j < 4; j++)
                Ps[(tx*4 + j)*65 + r] = s[i][j];
        }
        __syncthreads();

        // GEMM2: O[64][128] += P[64][64] @ V[64][128], with rescale
#pragma unroll
        for (int rr = 0; rr < 8; rr++) {
            float corr = c_s[ty2*8 + rr];
            acc[rr][0] *= corr; acc[rr][1] *= corr;
            acc[rr][2] *= corr; acc[rr][3] *= corr;
        }
#pragma unroll 8
        for (int kk = 0; kk < 64; kk++) {
            float4 bv = *(const float4*)&Vs[kk*128 + tx2*4];
#pragma unroll
            for (int rr = 0; rr < 8; rr++) {
                float a = Ps[kk*65 + ty2*8 + rr];
                acc[rr][0] += a * bv.x; acc[rr][1] += a * bv.y;
                acc[rr][2] += a * bv.z; acc[rr][3] += a * bv.w;
            }
        }

        // After the causal tiles: if some row never saw a real (un-masked)
        // score, its softmax is over ALL mask==0 keys -> extend over all tiles.
        if (kt == kt_end && !extended) {
            int pred = (tid < 64) && (m_s[tid] < -1e8f);
            if (__syncthreads_or(pred)) kt_end = 15;
            extended = true;
        }
    }

    float* og = g_o + (b*TT)*TS + h*EE;
#pragma unroll
    for (int rr = 0; rr < 8; rr++) {
        int r = ty2*8 + rr;
        float inv = 1.f / l_s[r];
        float4 o = make_float4(acc[rr][0]*inv, acc[rr][1]*inv,
                               acc[rr][2]*inv, acc[rr][3]*inv);
        *(float4*)&og[(qt*64 + r)*TS + tx2*4] = o;
    }
}

// ---------------------------------------------------------------------------
extern "C" void kernel_launch(void* const* d_in, const int* in_sizes, int n_in,
                              void* d_out, int out_size)
{
    const float* x    = (const float*)d_in[0];
    const int*   mask = (const int*)  d_in[1];
    const float* Wk   = (const float*)d_in[2];
    const float* Wq   = (const float*)d_in[3];
    const float* Wv   = (const float*)d_in[4];
    const float* Wu   = (const float*)d_in[5];
    const float* bu   = (const float*)d_in[6];
    float* out = (float*)d_out;

    float *q, *k, *v, *o;
    cudaGetSymbolAddress((void**)&q, g_q);
    cudaGetSymbolAddress((void**)&k, g_k);
    cudaGetSymbolAddress((void**)&v, g_v);
    cudaGetSymbolAddress((void**)&o, g_o);

    const int M = BB*TT;  // 8192

    // QKV projections: (8192,128) @ (1024,128)^T -> (8192,1024) == (b,t,h,e)
    dim3 gp(M/128, (HH*EE)/64);
    sgemm_nt<<<gp, 256>>>(x, Wq, q, nullptr, M, HH*EE, EE);
    sgemm_nt<<<gp, 256>>>(x, Wk, k, nullptr, M, HH*EE, EE);
    sgemm_nt<<<gp, 256>>>(x, Wv, v, nullptr, M, HH*EE, EE);

    // Attention
    size_t smem = (size_t)(128*64 + 128*64 + 64*128 + 64*65 + 3*64) * sizeof(float);
    cudaFuncSetAttribute(attn_kernel, cudaFuncAttributeMaxDynamicSharedMemorySize, (int)smem);
    dim3 ga(TT/64, HH, BB);
    attn_kernel<<<ga, 256, smem>>>(mask);

    // Output projection: (8192,1024) @ (128,1024)^T + bu -> (8192,128)
    dim3 go(M/128, EE/64);
    sgemm_nt<<<go, 256>>>(o, Wu, out, bu, M, EE, HH*EE);
}

// round 4
// speedup vs baseline: 3.4557x; 3.4557x over previous
#include <cuda_runtime.h>
#include <math.h>

#define BB 8
#define TT 1024
#define EE 128
#define HH 8
#define TS (HH*EE)   // 1024

// Scratch (allocation-free)
__device__ float g_q[BB*TT*TS/ (TS/ (HH*EE)) ];  // placeholder avoided below
// (real definitions)
#undef  QSIZE
__device__ float g_qbuf[BB*TT*HH*EE];
__device__ float g_kbuf[BB*TT*HH*EE];
__device__ float g_vbuf[BB*TT*HH*EE];
__device__ float g_obuf[BB*TT*HH*EE];
__device__ unsigned g_maskp[TT*TT/32];

// ---------------------------------------------------------------------------
// helpers
// ---------------------------------------------------------------------------
__device__ __forceinline__ unsigned f2tf(float x) {
    unsigned r; asm("cvt.rna.tf32.f32 %0, %1;" : "=r"(r) : "f"(x)); return r;
}
__device__ __forceinline__ float tf2f(float x) {  // convert and keep as float bits
    return __uint_as_float(f2tf(x));
}
__device__ __forceinline__ void mma8(float* d, unsigned a0, unsigned a1,
                                     unsigned a2, unsigned a3,
                                     unsigned b0, unsigned b1) {
    asm("mma.sync.aligned.m16n8k8.row.col.f32.tf32.tf32.f32 "
        "{%0,%1,%2,%3}, {%4,%5,%6,%7}, {%8,%9}, {%0,%1,%2,%3};"
        : "+f"(d[0]), "+f"(d[1]), "+f"(d[2]), "+f"(d[3])
        : "r"(a0), "r"(a1), "r"(a2), "r"(a3), "r"(b0), "r"(b1));
}
__device__ __forceinline__ unsigned ldb(const float* p) { return __float_as_uint(*p); }

// ---------------------------------------------------------------------------
// mask packing: int32 [T][T] -> bitmask [T][T/32]
// ---------------------------------------------------------------------------
__global__ void pack_mask(const int* __restrict__ mask) {
    int w = blockIdx.x * blockDim.x + threadIdx.x;
    if (w >= TT*TT/32) return;
    const int* src = mask + w*32;
    unsigned bits = 0;
#pragma unroll
    for (int i = 0; i < 32; i++) bits |= (src[i] != 0 ? 1u : 0u) << i;
    g_maskp[w] = bits;
}

// ---------------------------------------------------------------------------
// tf32 GEMM body: C[M,N] = A[M,K] @ W[N,K]^T (+bias).
// Block tile 128x64, 8 warps each m16 x n64, k-tiles of 128.
// ---------------------------------------------------------------------------
__device__ __forceinline__ void gemm_body(
    const float* __restrict__ A, const float* __restrict__ W,
    float* __restrict__ C, const float* __restrict__ bias,
    int N, int K, int bm, int bn, float* As, float* Ws)
{
    const int tid = threadIdx.x, lane = tid & 31, wp = tid >> 5;
    const int g = lane >> 2, c = lane & 3;

    float acc[8][4];
#pragma unroll
    for (int i = 0; i < 8; i++)
#pragma unroll
        for (int j = 0; j < 4; j++) acc[i][j] = 0.f;

    for (int k0 = 0; k0 < K; k0 += 128) {
        __syncthreads();
#pragma unroll
        for (int it = 0; it < 16; it++) {            // A tile 128x128
            int idx = tid + it*256;
            int r = idx >> 5, c4 = (idx & 31) << 2;
            float4 v = *(const float4*)&A[(size_t)(bm + r)*K + k0 + c4];
            float* dst = &As[r*132 + c4];
            dst[0] = tf2f(v.x); dst[1] = tf2f(v.y); dst[2] = tf2f(v.z); dst[3] = tf2f(v.w);
        }
#pragma unroll
        for (int it = 0; it < 8; it++) {             // W tile 64x128
            int idx = tid + it*256;
            int r = idx >> 5, c4 = (idx & 31) << 2;
            float4 v = *(const float4*)&W[(size_t)(bn + r)*K + k0 + c4];
            float* dst = &Ws[r*132 + c4];
            dst[0] = tf2f(v.x); dst[1] = tf2f(v.y); dst[2] = tf2f(v.z); dst[3] = tf2f(v.w);
        }
        __syncthreads();
#pragma unroll
        for (int ks = 0; ks < 16; ks++) {
            int kk = ks*8;
            const float* qa = &As[(wp*16 + g)*132 + kk + c];
            unsigned a0 = ldb(qa), a2 = ldb(qa + 4);
            unsigned a1 = ldb(qa + 8*132), a3 = ldb(qa + 8*132 + 4);
#pragma unroll
            for (int nt = 0; nt < 8; nt++) {
                const float* wb = &Ws[(nt*8 + g)*132 + kk + c];
                mma8(acc[nt], a0, a1, a2, a3, ldb(wb), ldb(wb + 4));
            }
        }
    }
#pragma unroll
    for (int nt = 0; nt < 8; nt++) {
        int col = bn + nt*8 + 2*c;
        float b0 = 0.f, b1 = 0.f;
        if (bias) { b0 = bias[col]; b1 = bias[col+1]; }
        int r0 = bm + wp*16 + g;
        *(float2*)&C[(size_t)r0*N + col]     = make_float2(acc[nt][0]+b0, acc[nt][1]+b1);
        *(float2*)&C[(size_t)(r0+8)*N + col] = make_float2(acc[nt][2]+b0, acc[nt][3]+b1);
    }
}

__global__ __launch_bounds__(256, 1) void qkv_gemm(
    const float* __restrict__ x,
    const float* __restrict__ Wq, const float* __restrict__ Wk,
    const float* __restrict__ Wv)
{
    extern __shared__ float sm[];
    const float* W = (blockIdx.z == 0) ? Wq : (blockIdx.z == 1) ? Wk : Wv;
    float* C = (blockIdx.z == 0) ? g_qbuf : (blockIdx.z == 1) ? g_kbuf : g_vbuf;
    gemm_body(x, W, C, nullptr, TS, EE, blockIdx.x*128, blockIdx.y*64,
              sm, sm + 128*132);
}

__global__ __launch_bounds__(256, 1) void out_gemm(
    const float* __restrict__ Wu, const float* __restrict__ bu,
    float* __restrict__ out)
{
    extern __shared__ float sm[];
    gemm_body(g_obuf, Wu, out, bu, EE, TS, blockIdx.x*128, blockIdx.y*64,
              sm, sm + 128*132);
}

// ---------------------------------------------------------------------------
// Flash attention, tf32 tensor cores. Block = 128 q-rows, 8 warps (m16 each).
// Key tiles of 64. Softmax state in registers (2 rows/lane, quad-replicated).
// ---------------------------------------------------------------------------
__global__ __launch_bounds__(256, 1) void attn_tc()
{
    extern __shared__ float sm[];
    float* Qs = sm;               // [128][132]
    float* Ks = Qs + 128*132;     // [64][132]
    float* Vs = Ks + 64*132;      // [64][136]
    float* Ps = Vs + 64*136;      // [128][68]

    const int tid = threadIdx.x, lane = tid & 31, wp = tid >> 5;
    const int g = lane >> 2, c = lane & 3;
    const int qt = blockIdx.x, h = blockIdx.y, b = blockIdx.z;

    const float* qg = g_qbuf + (size_t)(b*TT)*TS + h*EE;
    const float* kg = g_kbuf + (size_t)(b*TT)*TS + h*EE;
    const float* vg = g_vbuf + (size_t)(b*TT)*TS + h*EE;

    // Q tile 128x128 -> smem (tf32)
#pragma unroll
    for (int it = 0; it < 16; it++) {
        int idx = tid + it*256;
        int r = idx >> 5, c4 = (idx & 31) << 2;
        float4 v = *(const float4*)&qg[(size_t)(qt*128 + r)*TS + c4];
        float* dst = &Qs[r*132 + c4];
        dst[0] = tf2f(v.x); dst[1] = tf2f(v.y); dst[2] = tf2f(v.z); dst[3] = tf2f(v.w);
    }

    float m0 = -1e30f, m1 = -1e30f, l0 = 0.f, l1 = 0.f;
    float oacc[16][4];
#pragma unroll
    for (int i = 0; i < 16; i++)
#pragma unroll
        for (int j = 0; j < 4; j++) oacc[i][j] = 0.f;

    const int qa = qt*128 + wp*16 + g;
    const int qb = qa + 8;
    const unsigned* mra = g_maskp + qa*32;
    const unsigned* mrb = g_maskp + qb*32;
    const float scale = 0.08838834764831843f;   // 1/sqrt(128)

    int kt_end = 2*qt + 1;
    bool extended = false;

    for (int kt = 0; kt <= kt_end; kt++) {
        __syncthreads();
        // K,V tiles 64x128 -> smem (tf32)
#pragma unroll
        for (int it = 0; it < 8; it++) {
            int idx = tid + it*256;
            int r = idx >> 5, c4 = (idx & 31) << 2;
            float4 kv = *(const float4*)&kg[(size_t)(kt*64 + r)*TS + c4];
            float* kd = &Ks[r*132 + c4];
            kd[0] = tf2f(kv.x); kd[1] = tf2f(kv.y); kd[2] = tf2f(kv.z); kd[3] = tf2f(kv.w);
            float4 vv = *(const float4*)&vg[(size_t)(kt*64 + r)*TS + c4];
            float* vd = &Vs[r*136 + c4];
            vd[0] = tf2f(vv.x); vd[1] = tf2f(vv.y); vd[2] = tf2f(vv.z); vd[3] = tf2f(vv.w);
        }
        __syncthreads();

        // GEMM1: S (m16 x n64) = Q @ K^T
        float sacc[8][4];
#pragma unroll
        for (int i = 0; i < 8; i++)
#pragma unroll
            for (int j = 0; j < 4; j++) sacc[i][j] = 0.f;
#pragma unroll
        for (int ks = 0; ks < 16; ks++) {
            int kk = ks*8;
            const float* pa = &Qs[(wp*16 + g)*132 + kk + c];
            unsigned a0 = ldb(pa), a2 = ldb(pa + 4);
            unsigned a1 = ldb(pa + 8*132), a3 = ldb(pa + 8*132 + 4);
#pragma unroll
            for (int nt = 0; nt < 8; nt++) {
                const float* kb = &Ks[(nt*8 + g)*132 + kk + c];
                mma8(sacc[nt], a0, a1, a2, a3, ldb(kb), ldb(kb + 4));
            }
        }

        // softmax (exact reference mask semantics)
        unsigned wa0 = mra[kt*2], wa1 = mra[kt*2 + 1];
        unsigned wb0 = mrb[kt*2], wb1 = mrb[kt*2 + 1];
        float rm0 = -3e38f, rm1 = -3e38f;
#pragma unroll
        for (int nt = 0; nt < 8; nt++) {
#pragma unroll
            for (int j = 0; j < 2; j++) {
                int col = nt*8 + 2*c + j;
                int kkg = kt*64 + col;
                int bit = col & 31;
                unsigned wwa = (col < 32) ? wa0 : wa1;
                unsigned wwb = (col < 32) ? wb0 : wb1;
                float v0 = sacc[nt][j] * scale;
                if (kkg > qa) v0 = -1e30f;
                if (!((wwa >> bit) & 1)) v0 = -1e9f;
                sacc[nt][j] = v0; rm0 = fmaxf(rm0, v0);
                float v1 = sacc[nt][2+j] * scale;
                if (kkg > qb) v1 = -1e30f;
                if (!((wwb >> bit) & 1)) v1 = -1e9f;
                sacc[nt][2+j] = v1; rm1 = fmaxf(rm1, v1);
            }
        }
        rm0 = fmaxf(rm0, __shfl_xor_sync(0xffffffffu, rm0, 1));
        rm0 = fmaxf(rm0, __shfl_xor_sync(0xffffffffu, rm0, 2));
        rm1 = fmaxf(rm1, __shfl_xor_sync(0xffffffffu, rm1, 1));
        rm1 = fmaxf(rm1, __shfl_xor_sync(0xffffffffu, rm1, 2));
        float mn0 = fmaxf(m0, rm0), mn1 = fmaxf(m1, rm1);
        float rs0 = 0.f, rs1 = 0.f;
#pragma unroll
        for (int nt = 0; nt < 8; nt++) {
#pragma unroll
            for (int j = 0; j < 2; j++) {
                float p0 = __expf(sacc[nt][j]   - mn0); sacc[nt][j]   = p0; rs0 += p0;
                float p1 = __expf(sacc[nt][2+j] - mn1); sacc[nt][2+j] = p1; rs1 += p1;
            }
        }
        rs0 += __shfl_xor_sync(0xffffffffu, rs0, 1);
        rs0 += __shfl_xor_sync(0xffffffffu, rs0, 2);
        rs1 += __shfl_xor_sync(0xffffffffu, rs1, 1);
        rs1 += __shfl_xor_sync(0xffffffffu, rs1, 2);
        float corr0 = __expf(m0 - mn0), corr1 = __expf(m1 - mn1);
        l0 = l0*corr0 + rs0; l1 = l1*corr1 + rs1;
        m0 = mn0; m1 = mn1;

        // P -> per-warp smem slab (tf32), layout permute for PV mma
        __syncwarp();
#pragma unroll
        for (int nt = 0; nt < 8; nt++) {
            int col = nt*8 + 2*c;
            float* pr0 = &Ps[(wp*16 + g)*68 + col];
            float* pr1 = &Ps[(wp*16 + g + 8)*68 + col];
            pr0[0] = tf2f(sacc[nt][0]); pr0[1] = tf2f(sacc[nt][1]);
            pr1[0] = tf2f(sacc[nt][2]); pr1[1] = tf2f(sacc[nt][3]);
        }
        __syncwarp();

        // rescale O, then GEMM2: O += P @ V  (m16 x n128, k=64)
#pragma unroll
        for (int nt = 0; nt < 16; nt++) {
            oacc[nt][0] *= corr0; oacc[nt][1] *= corr0;
            oacc[nt][2] *= corr1; oacc[nt][3] *= corr1;
        }
#pragma unroll
        for (int ks = 0; ks < 8; ks++) {
            int kk = ks*8;
            const float* pa = &Ps[(wp*16 + g)*68 + kk + c];
            unsigned a0 = ldb(pa), a2 = ldb(pa + 4);
            unsigned a1 = ldb(pa + 8*68), a3 = ldb(pa + 8*68 + 4);
#pragma unroll
            for (int nt = 0; nt < 16; nt++) {
                const float* vb = &Vs[(kk + c)*136 + nt*8 + g];
                mma8(oacc[nt], a0, a1, a2, a3, ldb(vb), ldb(vb + 4*136));
            }
        }

        // extension: rows whose whole causal prefix was padding-masked
        if (kt == kt_end && !extended) {
            int pred = (m0 < -1e8f) || (m1 < -1e8f);
            if (__syncthreads_or(pred)) kt_end = TT/64 - 1;
            extended = true;
        }
    }

    float inv0 = 1.f / l0, inv1 = 1.f / l1;
    float* og = g_obuf + (size_t)(b*TT)*TS + h*EE;
#pragma unroll
    for (int nt = 0; nt < 16; nt++) {
        int col = nt*8 + 2*c;
        int r0 = qt*128 + wp*16 + g;
        *(float2*)&og[(size_t)r0*TS + col] =
            make_float2(oacc[nt][0]*inv0, oacc[nt][1]*inv0);
        *(float2*)&og[(size_t)(r0+8)*TS + col] =
            make_float2(oacc[nt][2]*inv1, oacc[nt][3]*inv1);
    }
}

// ---------------------------------------------------------------------------
extern "C" void kernel_launch(void* const* d_in, const int* in_sizes, int n_in,
                              void* d_out, int out_size)
{
    const float* x    = (const float*)d_in[0];
    const int*   mask = (const int*)  d_in[1];
    const float* Wk   = (const float*)d_in[2];
    const float* Wq   = (const float*)d_in[3];
    const float* Wv   = (const float*)d_in[4];
    const float* Wu   = (const float*)d_in[5];
    const float* bu   = (const float*)d_in[6];
    float* out = (float*)d_out;

    // mask bit-packing
    pack_mask<<<(TT*TT/32 + 255)/256, 256>>>(mask);

    const int gemm_smem = (128*132 + 64*132) * sizeof(float);     // ~101 KB
    const int attn_smem = (128*132 + 64*132 + 64*136 + 128*68) * sizeof(float); // ~171 KB
    cudaFuncSetAttribute(qkv_gemm, cudaFuncAttributeMaxDynamicSharedMemorySize, gemm_smem);
    cudaFuncSetAttribute(out_gemm, cudaFuncAttributeMaxDynamicSharedMemorySize, gemm_smem);
    cudaFuncSetAttribute(attn_tc,  cudaFuncAttributeMaxDynamicSharedMemorySize, attn_smem);

    // QKV projections (fused over z): (8192,128)@(1024,128)^T
    dim3 gq(BB*TT/128, TS/64, 3);
    qkv_gemm<<<gq, 256, gemm_smem>>>(x, Wq, Wk, Wv);

    // attention
    dim3 ga(TT/128, HH, BB);
    attn_tc<<<ga, 256, attn_smem>>>();

    // output projection: (8192,1024)@(128,1024)^T + bu
    dim3 go(BB*TT/128, EE/64);
    out_gemm<<<go, 256, gemm_smem>>>(Wu, bu, out);
}

// round 5
// speedup vs baseline: 5.7483x; 1.6634x over previous
#include <cuda_runtime.h>
#include <cuda_fp16.h>
#include <math.h>

#define BB 8
#define TT 1024
#define EE 128
#define HH 8
#define TS (HH*EE)   // 1024

// fp16 scratch (allocation-free)
__device__ __align__(16) __half g_xh [BB*TT*EE];
__device__ __align__(16) __half g_wqh[TS*EE];
__device__ __align__(16) __half g_wkh[TS*EE];
__device__ __align__(16) __half g_wvh[TS*EE];
__device__ __align__(16) __half g_wuh[EE*TS];
__device__ __align__(16) __half g_qh [BB*TT*TS];
__device__ __align__(16) __half g_kh [BB*TT*TS];
__device__ __align__(16) __half g_vT [BB*HH*EE*TT];   // [b,h,d,t]
__device__ __align__(16) __half g_oh [BB*TT*TS];
__device__ unsigned g_maskp[TT*TT/32];

// ---------------------------------------------------------------------------
// helpers
// ---------------------------------------------------------------------------
__device__ __forceinline__ unsigned sptr(const void* p) {
    return (unsigned)__cvta_generic_to_shared(p);
}
__device__ __forceinline__ void cpa16(unsigned d, const void* g) {
    asm volatile("cp.async.cg.shared.global [%0], [%1], 16;\n" :: "r"(d), "l"(g));
}
#define CP_COMMIT() asm volatile("cp.async.commit_group;\n")
#define CP_WAIT0()  asm volatile("cp.async.wait_group 0;\n")
#define CP_WAIT1()  asm volatile("cp.async.wait_group 1;\n")

__device__ __forceinline__ unsigned ldh2(const __half* p) {
    return *(const unsigned*)p;
}
__device__ __forceinline__ void mma16(float* d, unsigned a0, unsigned a1,
                                      unsigned a2, unsigned a3,
                                      unsigned b0, unsigned b1) {
    asm("mma.sync.aligned.m16n8k16.row.col.f32.f16.f16.f32 "
        "{%0,%1,%2,%3}, {%4,%5,%6,%7}, {%8,%9}, {%0,%1,%2,%3};"
        : "+f"(d[0]), "+f"(d[1]), "+f"(d[2]), "+f"(d[3])
        : "r"(a0), "r"(a1), "r"(a2), "r"(a3), "r"(b0), "r"(b1));
}

// ---------------------------------------------------------------------------
// one-time conversions: x, weights -> fp16;  mask -> bitmask
// ---------------------------------------------------------------------------
__global__ void convert_inputs(const float* __restrict__ x,
                               const float* __restrict__ Wq,
                               const float* __restrict__ Wk,
                               const float* __restrict__ Wv,
                               const float* __restrict__ Wu) {
    int i = blockIdx.x * blockDim.x + threadIdx.x;
    if (i < BB*TT*EE) g_xh[i] = __float2half_rn(x[i]);
    if (i < TS*EE) {
        g_wqh[i] = __float2half_rn(Wq[i]);
        g_wkh[i] = __float2half_rn(Wk[i]);
        g_wvh[i] = __float2half_rn(Wv[i]);
        g_wuh[i] = __float2half_rn(Wu[i]);
    }
}

__global__ void pack_mask(const int* __restrict__ mask) {
    int w = blockIdx.x * blockDim.x + threadIdx.x;
    if (w >= TT*TT/32) return;
    const int* src = mask + w*32;
    unsigned bits = 0;
#pragma unroll
    for (int i = 0; i < 32; i++) bits |= (src[i] != 0 ? 1u : 0u) << i;
    g_maskp[w] = bits;
}

// ---------------------------------------------------------------------------
// QKV projection: C = x @ W^T, fp16 in/out. Block tile 128x128, K=128.
// z selects Q/K/V. V written transposed [b,h,d,t].
// ---------------------------------------------------------------------------
__global__ __launch_bounds__(256, 1) void qkv_gemm()
{
    extern __shared__ __half smh[];
    __half* As = smh;            // [128][136]
    __half* Ws = smh + 128*136;  // [128][136]
    const int tid = threadIdx.x, lane = tid & 31, wp = tid >> 5;
    const int g = lane >> 2, c = lane & 3;
    const int bm = blockIdx.x*128, bn = blockIdx.y*128, z = blockIdx.z;
    const __half* W = (z == 0) ? g_wqh : (z == 1) ? g_wkh : g_wvh;

#pragma unroll
    for (int it = 0; it < 8; it++) {
        int id = tid + it*256, r = id >> 4, ch = id & 15;
        cpa16(sptr(&As[r*136 + ch*8]), &g_xh[(size_t)(bm + r)*EE + ch*8]);
        cpa16(sptr(&Ws[r*136 + ch*8]), &W[(size_t)(bn + r)*EE + ch*8]);
    }
    CP_COMMIT(); CP_WAIT0();
    __syncthreads();

    float acc[16][4];
#pragma unroll
    for (int i = 0; i < 16; i++)
#pragma unroll
        for (int j = 0; j < 4; j++) acc[i][j] = 0.f;

#pragma unroll
    for (int ks = 0; ks < 8; ks++) {
        const __half* pa = &As[(wp*16 + g)*136 + ks*16 + 2*c];
        unsigned a0 = ldh2(pa), a1 = ldh2(pa + 8*136);
        unsigned a2 = ldh2(pa + 8), a3 = ldh2(pa + 8*136 + 8);
#pragma unroll
        for (int nt = 0; nt < 16; nt++) {
            const __half* pb = &Ws[(nt*8 + g)*136 + ks*16 + 2*c];
            mma16(acc[nt], a0, a1, a2, a3, ldh2(pb), ldh2(pb + 8));
        }
    }

    const int r0 = bm + wp*16 + g;
    if (z < 2) {
        __half* dst = (z == 0) ? g_qh : g_kh;
#pragma unroll
        for (int nt = 0; nt < 16; nt++) {
            int col = bn + nt*8 + 2*c;
            *(__half2*)&dst[(size_t)r0*TS + col] =
                __floats2half2_rn(acc[nt][0], acc[nt][1]);
            *(__half2*)&dst[(size_t)(r0+8)*TS + col] =
                __floats2half2_rn(acc[nt][2], acc[nt][3]);
        }
    } else {
        int b = r0 >> 10, t = r0 & 1023;
#pragma unroll
        for (int nt = 0; nt < 16; nt++) {
            int col = bn + nt*8 + 2*c;
            int h = col >> 7, d = col & 127;
            __half* vt = &g_vT[(size_t)((b*HH + h)*EE + d)*TT + t];
            vt[0]      = __float2half_rn(acc[nt][0]);
            vt[TT]     = __float2half_rn(acc[nt][1]);
            vt[8]      = __float2half_rn(acc[nt][2]);
            vt[TT + 8] = __float2half_rn(acc[nt][3]);
        }
    }
}

// ---------------------------------------------------------------------------
// Flash attention, fp16 mma, cp.async double-buffered K/V tiles.
// Block = 128 q-rows x (head, batch). 8 warps, warp owns m16.
// ---------------------------------------------------------------------------
__global__ __launch_bounds__(256, 1) void attn_tc()
{
    extern __shared__ __half smh[];
    __half* Qs = smh;                  // [128][136]
    __half* Ks = Qs + 128*136;         // 2 x [64][136]
    __half* Vs = Ks + 2*64*136;        // 2 x [128][72]   (V^T: d rows, key cols)
    __half* Ps = Vs + 2*128*72;        // [128][72]

    const int tid = threadIdx.x, lane = tid & 31, wp = tid >> 5;
    const int g = lane >> 2, c = lane & 3;
    const int qt = blockIdx.x, h = blockIdx.y, b = blockIdx.z;

    const __half* qg = g_qh + (size_t)(b*TT + qt*128)*TS + h*EE;
    const __half* kg = g_kh + (size_t)(b*TT)*TS + h*EE;
    const __half* vg = g_vT + (size_t)((b*HH + h)*EE)*TT;

    const int qa = qt*128 + wp*16 + g;
    const int qb = qa + 8;

    // --- static extension predicate: row's whole causal prefix mask==0? ---
    bool need = false;
    if (c == 0) {
#pragma unroll
        for (int rr = 0; rr < 2; rr++) {
            int q = (rr == 0) ? qa : qb;
            const unsigned* mr = g_maskp + q*32;
            int wlast = q >> 5;
            bool allz = true;
            for (int w = 0; w <= wlast; w++) {
                unsigned m = mr[w];
                if (w == wlast) m &= (0xFFFFFFFFu >> (31 - (q & 31)));
                allz &= (m == 0);
            }
            need |= allz;
        }
    }
    const int kt_last = __syncthreads_or(need) ? (TT/64 - 1) : 2*qt + 1;

    // --- prologue: Q + K0 + V0 ---
#pragma unroll
    for (int it = 0; it < 8; it++) {
        int id = tid + it*256, r = id >> 4, ch = id & 15;
        cpa16(sptr(&Qs[r*136 + ch*8]), qg + (size_t)r*TS + ch*8);
    }
#pragma unroll
    for (int it = 0; it < 4; it++) {
        int id = tid + it*256, r = id >> 4, ch = id & 15;
        cpa16(sptr(&Ks[r*136 + ch*8]), kg + (size_t)r*TS + ch*8);
    }
#pragma unroll
    for (int it = 0; it < 4; it++) {
        int id = tid + it*256, r = id >> 3, ch = id & 7;
        cpa16(sptr(&Vs[r*72 + ch*8]), vg + (size_t)r*TT + ch*8);
    }
    CP_COMMIT();

    float m0 = -1e30f, m1 = -1e30f, l0 = 0.f, l1 = 0.f;
    float oacc[16][4];
#pragma unroll
    for (int i = 0; i < 16; i++)
#pragma unroll
        for (int j = 0; j < 4; j++) oacc[i][j] = 0.f;

    const unsigned* mra = g_maskp + qa*32;
    const unsigned* mrb = g_maskp + qb*32;
    const float scale = 0.08838834764831843f;   // 1/sqrt(128)

    for (int kt = 0; kt <= kt_last; kt++) {
        const int cur = kt & 1;
        __syncthreads();                         // prev compute done before refill
        if (kt + 1 <= kt_last) {
            const int nb = cur ^ 1;
            __half* Kd = Ks + nb*64*136;
            __half* Vd = Vs + nb*128*72;
            const __half* ksg = kg + (size_t)(kt+1)*64*TS;
            const __half* vsg = vg + (kt+1)*64;
#pragma unroll
            for (int it = 0; it < 4; it++) {
                int id = tid + it*256, r = id >> 4, ch = id & 15;
                cpa16(sptr(&Kd[r*136 + ch*8]), ksg + (size_t)r*TS + ch*8);
            }
#pragma unroll
            for (int it = 0; it < 4; it++) {
                int id = tid + it*256, r = id >> 3, ch = id & 7;
                cpa16(sptr(&Vd[r*72 + ch*8]), vsg + (size_t)r*TT + ch*8);
            }
            CP_COMMIT();
            CP_WAIT1();
        } else {
            CP_WAIT0();
        }
        __syncthreads();

        const __half* Kc = Ks + cur*64*136;
        const __half* Vc = Vs + cur*128*72;

        // GEMM1: S (m16 x n64) = Q @ K^T
        float sacc[8][4];
#pragma unroll
        for (int i = 0; i < 8; i++)
#pragma unroll
            for (int j = 0; j < 4; j++) sacc[i][j] = 0.f;
#pragma unroll
        for (int ks = 0; ks < 8; ks++) {
            const __half* pa = &Qs[(wp*16 + g)*136 + ks*16 + 2*c];
            unsigned a0 = ldh2(pa), a1 = ldh2(pa + 8*136);
            unsigned a2 = ldh2(pa + 8), a3 = ldh2(pa + 8*136 + 8);
#pragma unroll
            for (int nt = 0; nt < 8; nt++) {
                const __half* kb = &Kc[(nt*8 + g)*136 + ks*16 + 2*c];
                mma16(sacc[nt], a0, a1, a2, a3, ldh2(kb), ldh2(kb + 8));
            }
        }

        // softmax with exact reference mask semantics
        unsigned wa0 = mra[kt*2], wa1 = mra[kt*2 + 1];
        unsigned wb0 = mrb[kt*2], wb1 = mrb[kt*2 + 1];
        float rm0 = -3e38f, rm1 = -3e38f;
#pragma unroll
        for (int nt = 0; nt < 8; nt++) {
#pragma unroll
            for (int j = 0; j < 2; j++) {
                int col = nt*8 + 2*c + j;
                int kkg = kt*64 + col;
                int bit = col & 31;
                unsigned wwa = (col < 32) ? wa0 : wa1;
                unsigned wwb = (col < 32) ? wb0 : wb1;
                float v0 = sacc[nt][j] * scale;
                if (kkg > qa) v0 = -1e30f;                // causal first
                if (!((wwa >> bit) & 1)) v0 = -1e9f;      // padding overwrites
                sacc[nt][j] = v0; rm0 = fmaxf(rm0, v0);
                float v1 = sacc[nt][2+j] * scale;
                if (kkg > qb) v1 = -1e30f;
                if (!((wwb >> bit) & 1)) v1 = -1e9f;
                sacc[nt][2+j] = v1; rm1 = fmaxf(rm1, v1);
            }
        }
        rm0 = fmaxf(rm0, __shfl_xor_sync(0xffffffffu, rm0, 1));
        rm0 = fmaxf(rm0, __shfl_xor_sync(0xffffffffu, rm0, 2));
        rm1 = fmaxf(rm1, __shfl_xor_sync(0xffffffffu, rm1, 1));
        rm1 = fmaxf(rm1, __shfl_xor_sync(0xffffffffu, rm1, 2));
        float mn0 = fmaxf(m0, rm0), mn1 = fmaxf(m1, rm1);
        float rs0 = 0.f, rs1 = 0.f;
#pragma unroll
        for (int nt = 0; nt < 8; nt++) {
#pragma unroll
            for (int j = 0; j < 2; j++) {
                float p0 = __expf(sacc[nt][j]   - mn0); sacc[nt][j]   = p0; rs0 += p0;
                float p1 = __expf(sacc[nt][2+j] - mn1); sacc[nt][2+j] = p1; rs1 += p1;
            }
        }
        rs0 += __shfl_xor_sync(0xffffffffu, rs0, 1);
        rs0 += __shfl_xor_sync(0xffffffffu, rs0, 2);
        rs1 += __shfl_xor_sync(0xffffffffu, rs1, 1);
        rs1 += __shfl_xor_sync(0xffffffffu, rs1, 2);
        float corr0 = __expf(m0 - mn0), corr1 = __expf(m1 - mn1);
        l0 = l0*corr0 + rs0; l1 = l1*corr1 + rs1;
        m0 = mn0; m1 = mn1;

        // P -> per-warp smem slab (fp16)
        __syncwarp();
#pragma unroll
        for (int nt = 0; nt < 8; nt++) {
            int col = nt*8 + 2*c;
            *(__half2*)&Ps[(wp*16 + g)*72 + col] =
                __floats2half2_rn(sacc[nt][0], sacc[nt][1]);
            *(__half2*)&Ps[(wp*16 + g + 8)*72 + col] =
                __floats2half2_rn(sacc[nt][2], sacc[nt][3]);
        }
        __syncwarp();

        // rescale O, then GEMM2: O (m16 x n128) += P @ V
#pragma unroll
        for (int nt = 0; nt < 16; nt++) {
            oacc[nt][0] *= corr0; oacc[nt][1] *= corr0;
            oacc[nt][2] *= corr1; oacc[nt][3] *= corr1;
        }
#pragma unroll
        for (int ks = 0; ks < 4; ks++) {
            const __half* pa = &Ps[(wp*16 + g)*72 + ks*16 + 2*c];
            unsigned a0 = ldh2(pa), a1 = ldh2(pa + 8*72);
            unsigned a2 = ldh2(pa + 8), a3 = ldh2(pa + 8*72 + 8);
#pragma unroll
            for (int nt = 0; nt < 16; nt++) {
                const __half* vb = &Vc[(nt*8 + g)*72 + ks*16 + 2*c];
                mma16(oacc[nt], a0, a1, a2, a3, ldh2(vb), ldh2(vb + 8));
            }
        }
    }

    float inv0 = 1.f / l0, inv1 = 1.f / l1;
    size_t obase = (size_t)(b*TT + qt*128 + wp*16 + g)*TS + h*EE;
#pragma unroll
    for (int nt = 0; nt < 16; nt++) {
        int col = nt*8 + 2*c;
        *(__half2*)&g_oh[obase + col] =
            __floats2half2_rn(oacc[nt][0]*inv0, oacc[nt][1]*inv0);
        *(__half2*)&g_oh[obase + (size_t)8*TS + col] =
            __floats2half2_rn(oacc[nt][2]*inv1, oacc[nt][3]*inv1);
    }
}

// ---------------------------------------------------------------------------
// Output projection: out = O @ Wu^T + bu. fp16 in, fp32 out.
// Block tile 128x64, K=1024 in 8 pipelined k-tiles.
// ---------------------------------------------------------------------------
__global__ __launch_bounds__(256, 1) void out_gemm(const float* __restrict__ bu,
                                                   float* __restrict__ out)
{
    extern __shared__ __half smh[];
    __half* As = smh;                // 2 x [128][136]
    __half* Ws = smh + 2*128*136;    // 2 x [64][136]
    const int tid = threadIdx.x, lane = tid & 31, wp = tid >> 5;
    const int g = lane >> 2, c = lane & 3;
    const int bm = blockIdx.x*128, bn = blockIdx.y*64;

    // prologue: k-tile 0
#pragma unroll
    for (int it = 0; it < 8; it++) {
        int id = tid + it*256, r = id >> 4, ch = id & 15;
        cpa16(sptr(&As[r*136 + ch*8]), &g_oh[(size_t)(bm + r)*TS + ch*8]);
    }
#pragma unroll
    for (int it = 0; it < 4; it++) {
        int id = tid + it*256, r = id >> 4, ch = id & 15;
        cpa16(sptr(&Ws[r*136 + ch*8]), &g_wuh[(size_t)(bn + r)*TS + ch*8]);
    }
    CP_COMMIT();

    float acc[8][4];
#pragma unroll
    for (int i = 0; i < 8; i++)
#pragma unroll
        for (int j = 0; j < 4; j++) acc[i][j] = 0.f;

    for (int kt = 0; kt < 8; kt++) {
        const int cur = kt & 1;
        __syncthreads();
        if (kt < 7) {
            const int nb = cur ^ 1;
            int k0 = (kt + 1)*128;
            __half* Ad = As + nb*128*136;
            __half* Wd = Ws + nb*64*136;
#pragma unroll
            for (int it = 0; it < 8; it++) {
                int id = tid + it*256, r = id >> 4, ch = id & 15;
                cpa16(sptr(&Ad[r*136 + ch*8]),
                      &g_oh[(size_t)(bm + r)*TS + k0 + ch*8]);
            }
#pragma unroll
            for (int it = 0; it < 4; it++) {
                int id = tid + it*256, r = id >> 4, ch = id & 15;
                cpa16(sptr(&Wd[r*136 + ch*8]),
                      &g_wuh[(size_t)(bn + r)*TS + k0 + ch*8]);
            }
            CP_COMMIT();
            CP_WAIT1();
        } else {
            CP_WAIT0();
        }
        __syncthreads();

        const __half* Ac = As + cur*128*136;
        const __half* Wc = Ws + cur*64*136;
#pragma unroll
        for (int ks = 0; ks < 8; ks++) {
            const __half* pa = &Ac[(wp*16 + g)*136 + ks*16 + 2*c];
            unsigned a0 = ldh2(pa), a1 = ldh2(pa + 8*136);
            unsigned a2 = ldh2(pa + 8), a3 = ldh2(pa + 8*136 + 8);
#pragma unroll
            for (int nt = 0; nt < 8; nt++) {
                const __half* pb = &Wc[(nt*8 + g)*136 + ks*16 + 2*c];
                mma16(acc[nt], a0, a1, a2, a3, ldh2(pb), ldh2(pb + 8));
            }
        }
    }

    const int r0 = bm + wp*16 + g;
#pragma unroll
    for (int nt = 0; nt < 8; nt++) {
        int col = bn + nt*8 + 2*c;
        float b0 = bu[col], b1 = bu[col + 1];
        *(float2*)&out[(size_t)r0*EE + col] =
            make_float2(acc[nt][0] + b0, acc[nt][1] + b1);
        *(float2*)&out[(size_t)(r0+8)*EE + col] =
            make_float2(acc[nt][2] + b0, acc[nt][3] + b1);
    }
}

// ---------------------------------------------------------------------------
extern "C" void kernel_launch(void* const* d_in, const int* in_sizes, int n_in,
                              void* d_out, int out_size)
{
    const float* x    = (const float*)d_in[0];
    const int*   mask = (const int*)  d_in[1];
    const float* Wk   = (const float*)d_in[2];
    const float* Wq   = (const float*)d_in[3];
    const float* Wv   = (const float*)d_in[4];
    const float* Wu   = (const float*)d_in[5];
    const float* bu   = (const float*)d_in[6];
    float* out = (float*)d_out;

    convert_inputs<<<(BB*TT*EE + 255)/256, 256>>>(x, Wq, Wk, Wv, Wu);
    pack_mask<<<(TT*TT/32 + 255)/256, 256>>>(mask);

    const int qkv_smem  = (128*136 + 128*136) * sizeof(__half);               // 69.6 KB
    const int attn_smem = (128*136 + 2*64*136 + 2*128*72 + 128*72) * sizeof(__half); // 124.9 KB
    const int outp_smem = (2*128*136 + 2*64*136) * sizeof(__half);            // 104.4 KB
    cudaFuncSetAttribute(qkv_gemm, cudaFuncAttributeMaxDynamicSharedMemorySize, qkv_smem);
    cudaFuncSetAttribute(attn_tc,  cudaFuncAttributeMaxDynamicSharedMemorySize, attn_smem);
    cudaFuncSetAttribute(out_gemm, cudaFuncAttributeMaxDynamicSharedMemorySize, outp_smem);

    dim3 gq(BB*TT/128, TS/128, 3);
    qkv_gemm<<<gq, 256, qkv_smem>>>();

    dim3 ga(TT/128, HH, BB);
    attn_tc<<<ga, 256, attn_smem>>>();

    dim3 go(BB*TT/128, EE/64);
    out_gemm<<<go, 256, outp_smem>>>(bu, out);
}

// round 6
// speedup vs baseline: 6.2069x; 1.0798x over previous
#include <cuda_runtime.h>
#include <cuda_fp16.h>
#include <math.h>

#define BB 8
#define TT 1024
#define EE 128
#define HH 8
#define TS (HH*EE)   // 1024

// fp16 scratch (allocation-free)
__device__ __align__(16) __half g_xh [BB*TT*EE];
__device__ __align__(16) __half g_wqh[TS*EE];
__device__ __align__(16) __half g_wkh[TS*EE];
__device__ __align__(16) __half g_wvh[TS*EE];
__device__ __align__(16) __half g_wuh[EE*TS];
__device__ __align__(16) __half g_qh [BB*TT*TS];   // pre-scaled by 1/sqrt(128)
__device__ __align__(16) __half g_kh [BB*TT*TS];
__device__ __align__(16) __half g_vT [BB*HH*EE*TT];  // [b,h,d,t]
__device__ __align__(16) __half g_oh [BB*TT*TS];
__device__ unsigned g_maskp[TT*TT/32];

// ---------------------------------------------------------------------------
// helpers
// ---------------------------------------------------------------------------
__device__ __forceinline__ unsigned sptr(const void* p) {
    return (unsigned)__cvta_generic_to_shared(p);
}
__device__ __forceinline__ void cpa16(unsigned d, const void* g) {
    asm volatile("cp.async.cg.shared.global [%0], [%1], 16;\n" :: "r"(d), "l"(g));
}
#define CP_COMMIT() asm volatile("cp.async.commit_group;\n")
#define CP_WAIT0()  asm volatile("cp.async.wait_group 0;\n")
#define CP_WAIT1()  asm volatile("cp.async.wait_group 1;\n")

__device__ __forceinline__ unsigned ldh2(const __half* p) {
    return *(const unsigned*)p;
}
__device__ __forceinline__ void ldm_x4(unsigned& r0, unsigned& r1,
                                       unsigned& r2, unsigned& r3, unsigned a) {
    asm volatile("ldmatrix.sync.aligned.m8n8.x4.shared.b16 {%0,%1,%2,%3}, [%4];"
        : "=r"(r0), "=r"(r1), "=r"(r2), "=r"(r3) : "r"(a));
}
__device__ __forceinline__ void mma16(float* d, unsigned a0, unsigned a1,
                                      unsigned a2, unsigned a3,
                                      unsigned b0, unsigned b1) {
    asm("mma.sync.aligned.m16n8k16.row.col.f32.f16.f16.f32 "
        "{%0,%1,%2,%3}, {%4,%5,%6,%7}, {%8,%9}, {%0,%1,%2,%3};"
        : "+f"(d[0]), "+f"(d[1]), "+f"(d[2]), "+f"(d[3])
        : "r"(a0), "r"(a1), "r"(a2), "r"(a3), "r"(b0), "r"(b1));
}
__device__ __forceinline__ unsigned f2h2(float lo, float hi) {
    __half2 h = __floats2half2_rn(lo, hi);
    return *(unsigned*)&h;
}

// ---------------------------------------------------------------------------
// one-time conversions
// ---------------------------------------------------------------------------
__global__ void convert_inputs(const float* __restrict__ x,
                               const float* __restrict__ Wq,
                               const float* __restrict__ Wk,
                               const float* __restrict__ Wv,
                               const float* __restrict__ Wu) {
    int i = blockIdx.x * blockDim.x + threadIdx.x;
    if (i < BB*TT*EE) g_xh[i] = __float2half_rn(x[i]);
    if (i < TS*EE) {
        g_wqh[i] = __float2half_rn(Wq[i]);
        g_wkh[i] = __float2half_rn(Wk[i]);
        g_wvh[i] = __float2half_rn(Wv[i]);
        g_wuh[i] = __float2half_rn(Wu[i]);
    }
}

__global__ void pack_mask(const int* __restrict__ mask) {
    int w = blockIdx.x * blockDim.x + threadIdx.x;
    if (w >= TT*TT/32) return;
    const int* src = mask + w*32;
    unsigned bits = 0;
#pragma unroll
    for (int i = 0; i < 32; i++) bits |= (src[i] != 0 ? 1u : 0u) << i;
    g_maskp[w] = bits;
}

// ---------------------------------------------------------------------------
// QKV projection: C = x @ W^T. Block tile 128x64, K=128, 2 CTAs/SM.
// z selects Q/K/V; Q pre-scaled by 1/sqrt(128); V written transposed [b,h,d,t].
// ---------------------------------------------------------------------------
__global__ __launch_bounds__(256, 2) void qkv_gemm()
{
    extern __shared__ __half smh[];
    __half* As = smh;            // [128][136]
    __half* Ws = smh + 128*136;  // [64][136]
    const int tid = threadIdx.x, lane = tid & 31, wp = tid >> 5;
    const int g = lane >> 2, c = lane & 3;
    const int brow = lane & 7;
    const int bcol = (lane & 8) ? 8 : 0;
    const int bsel = (lane >> 4) & 1;
    const int bm = blockIdx.x*128, bn = blockIdx.y*64, z = blockIdx.z;
    const __half* W = (z == 0) ? g_wqh : (z == 1) ? g_wkh : g_wvh;

#pragma unroll
    for (int it = 0; it < 8; it++) {
        int id = tid + it*256, r = id >> 4, ch = id & 15;
        cpa16(sptr(&As[r*136 + ch*8]), &g_xh[(size_t)(bm + r)*EE + ch*8]);
    }
#pragma unroll
    for (int it = 0; it < 4; it++) {
        int id = tid + it*256, r = id >> 4, ch = id & 15;
        cpa16(sptr(&Ws[r*136 + ch*8]), &W[(size_t)(bn + r)*EE + ch*8]);
    }
    CP_COMMIT(); CP_WAIT0();
    __syncthreads();

    float acc[8][4];
#pragma unroll
    for (int i = 0; i < 8; i++)
#pragma unroll
        for (int j = 0; j < 4; j++) acc[i][j] = 0.f;

#pragma unroll
    for (int ks = 0; ks < 8; ks++) {
        const __half* pa = &As[(wp*16 + g)*136 + ks*16 + 2*c];
        unsigned a0 = ldh2(pa), a1 = ldh2(pa + 8*136);
        unsigned a2 = ldh2(pa + 8), a3 = ldh2(pa + 8*136 + 8);
#pragma unroll
        for (int ntp = 0; ntp < 4; ntp++) {
            unsigned b0, b1, b2, b3;
            ldm_x4(b0, b1, b2, b3,
                   sptr(&Ws[((ntp*2 + bsel)*8 + brow)*136 + ks*16 + bcol]));
            mma16(acc[ntp*2],     a0, a1, a2, a3, b0, b1);
            mma16(acc[ntp*2 + 1], a0, a1, a2, a3, b2, b3);
        }
    }

    const int r0 = bm + wp*16 + g;
    if (z < 2) {
        __half* dst = (z == 0) ? g_qh : g_kh;
        const float sc = (z == 0) ? 0.08838834764831843f : 1.0f;  // 1/sqrt(128)
#pragma unroll
        for (int nt = 0; nt < 8; nt++) {
            int col = bn + nt*8 + 2*c;
            *(__half2*)&dst[(size_t)r0*TS + col] =
                __floats2half2_rn(acc[nt][0]*sc, acc[nt][1]*sc);
            *(__half2*)&dst[(size_t)(r0+8)*TS + col] =
                __floats2half2_rn(acc[nt][2]*sc, acc[nt][3]*sc);
        }
    } else {
        int b = r0 >> 10, t = r0 & 1023;
#pragma unroll
        for (int nt = 0; nt < 8; nt++) {
            int col = bn + nt*8 + 2*c;
            int h = col >> 7, d = col & 127;
            __half* vt = &g_vT[(size_t)((b*HH + h)*EE + d)*TT + t];
            vt[0]      = __float2half_rn(acc[nt][0]);
            vt[TT]     = __float2half_rn(acc[nt][1]);
            vt[8]      = __float2half_rn(acc[nt][2]);
            vt[TT + 8] = __float2half_rn(acc[nt][3]);
        }
    }
}

// ---------------------------------------------------------------------------
// Flash attention: fp16 mma, ldmatrix fragments, Q + P in registers,
// cp.async double-buffered K/V, paired q-tiles (qt, 7-qt) for balance.
// ---------------------------------------------------------------------------
__global__ __launch_bounds__(256, 1) void attn_tc()
{
    extern __shared__ __half smh[];
    __half* Qs = smh;                  // [128][136]
    __half* Ks = Qs + 128*136;         // 2 x [64][136]
    __half* Vs = Ks + 2*64*136;        // 2 x [128][72]  (V^T: d rows, t cols)

    const int tid = threadIdx.x, lane = tid & 31, wp = tid >> 5;
    const int g = lane >> 2, c = lane & 3;
    const int h = blockIdx.y, b = blockIdx.z;

    // ldmatrix lane addressing
    const int arow = (lane & 7) + ((lane & 8) ? 8 : 0);
    const int acol = (lane & 16) ? 8 : 0;
    const int brow = lane & 7;
    const int bcol = (lane & 8) ? 8 : 0;
    const int bsel = (lane >> 4) & 1;

    const __half* kg = g_kh + (size_t)(b*TT)*TS + h*EE;
    const __half* vg = g_vT + (size_t)((b*HH + h)*EE)*TT;

    for (int rep = 0; rep < 2; rep++) {
        const int qt = rep ? (7 - blockIdx.x) : blockIdx.x;
        const __half* qg = g_qh + (size_t)(b*TT + qt*128)*TS + h*EE;
        const int qa = qt*128 + wp*16 + g;
        const int qb = qa + 8;

        // static extension predicate: whole causal prefix padding-masked?
        bool need = false;
        if (c == 0) {
#pragma unroll
            for (int rr = 0; rr < 2; rr++) {
                int q = rr ? qb : qa;
                const unsigned* mr = g_maskp + q*32;
                int wlast = q >> 5;
                bool allz = true;
                for (int w = 0; w <= wlast; w++) {
                    unsigned m = mr[w];
                    if (w == wlast) m &= (0xFFFFFFFFu >> (31 - (q & 31)));
                    allz &= (m == 0);
                }
                need |= allz;
            }
        }
        // this barrier also guards smem reuse across reps
        const int kt_last = __syncthreads_or(need) ? (TT/64 - 1) : 2*qt + 1;

        // prologue: Q + K0 + V0
#pragma unroll
        for (int it = 0; it < 8; it++) {
            int id = tid + it*256, r = id >> 4, ch = id & 15;
            cpa16(sptr(&Qs[r*136 + ch*8]), qg + (size_t)r*TS + ch*8);
        }
#pragma unroll
        for (int it = 0; it < 4; it++) {
            int id = tid + it*256, r = id >> 4, ch = id & 15;
            cpa16(sptr(&Ks[r*136 + ch*8]), kg + (size_t)r*TS + ch*8);
        }
#pragma unroll
        for (int it = 0; it < 4; it++) {
            int id = tid + it*256, r = id >> 3, ch = id & 7;
            cpa16(sptr(&Vs[r*72 + ch*8]), vg + (size_t)r*TT + ch*8);
        }
        CP_COMMIT();
        CP_WAIT0();
        __syncthreads();

        // Q fragments -> registers (once per q-tile)
        unsigned qf[8][4];
#pragma unroll
        for (int ks = 0; ks < 8; ks++)
            ldm_x4(qf[ks][0], qf[ks][1], qf[ks][2], qf[ks][3],
                   sptr(&Qs[(wp*16 + arow)*136 + ks*16 + acol]));

        float m0 = -1e30f, m1 = -1e30f, l0 = 0.f, l1 = 0.f;
        float oacc[16][4];
#pragma unroll
        for (int i = 0; i < 16; i++)
#pragma unroll
            for (int j = 0; j < 4; j++) oacc[i][j] = 0.f;

        const unsigned* mra = g_maskp + qa*32;
        const unsigned* mrb = g_maskp + qb*32;

        for (int kt = 0; kt <= kt_last; kt++) {
            const int cur = kt & 1;
            __syncthreads();                 // prev compute done before refill
            if (kt + 1 <= kt_last) {
                const int nb = cur ^ 1;
                __half* Kd = Ks + nb*64*136;
                __half* Vd = Vs + nb*128*72;
                const __half* ksg = kg + (size_t)(kt+1)*64*TS;
                const __half* vsg = vg + (kt+1)*64;
#pragma unroll
                for (int it = 0; it < 4; it++) {
                    int id = tid + it*256, r = id >> 4, ch = id & 15;
                    cpa16(sptr(&Kd[r*136 + ch*8]), ksg + (size_t)r*TS + ch*8);
                }
#pragma unroll
                for (int it = 0; it < 4; it++) {
                    int id = tid + it*256, r = id >> 3, ch = id & 7;
                    cpa16(sptr(&Vd[r*72 + ch*8]), vsg + (size_t)r*TT + ch*8);
                }
                CP_COMMIT();
                CP_WAIT1();
            } else {
                CP_WAIT0();
            }
            __syncthreads();

            const __half* Kc = Ks + cur*64*136;
            const __half* Vc = Vs + cur*128*72;

            // GEMM1: S (m16 x n64) = Q @ K^T   (ldmatrix B frags)
            float sacc[8][4];
#pragma unroll
            for (int i = 0; i < 8; i++)
#pragma unroll
                for (int j = 0; j < 4; j++) sacc[i][j] = 0.f;
#pragma unroll
            for (int ks = 0; ks < 8; ks++) {
#pragma unroll
                for (int ntp = 0; ntp < 4; ntp++) {
                    unsigned b0, b1, b2, b3;
                    ldm_x4(b0, b1, b2, b3,
                        sptr(&Kc[((ntp*2 + bsel)*8 + brow)*136 + ks*16 + bcol]));
                    mma16(sacc[ntp*2],     qf[ks][0], qf[ks][1], qf[ks][2], qf[ks][3], b0, b1);
                    mma16(sacc[ntp*2 + 1], qf[ks][0], qf[ks][1], qf[ks][2], qf[ks][3], b2, b3);
                }
            }

            // softmax (scale pre-folded into Q; exact reference mask semantics)
            unsigned wa0 = mra[kt*2], wa1 = mra[kt*2 + 1];
            unsigned wb0 = mrb[kt*2], wb1 = mrb[kt*2 + 1];
            float rm0 = -3e38f, rm1 = -3e38f;
#pragma unroll
            for (int nt = 0; nt < 8; nt++) {
#pragma unroll
                for (int j = 0; j < 2; j++) {
                    int col = nt*8 + 2*c + j;
                    int kkg = kt*64 + col;
                    int bit = col & 31;
                    unsigned wwa = (col < 32) ? wa0 : wa1;
                    unsigned wwb = (col < 32) ? wb0 : wb1;
                    float v0 = sacc[nt][j];
                    if (kkg > qa) v0 = -1e30f;              // causal first
                    if (!((wwa >> bit) & 1)) v0 = -1e9f;    // padding overwrites
                    sacc[nt][j] = v0; rm0 = fmaxf(rm0, v0);
                    float v1 = sacc[nt][2+j];
                    if (kkg > qb) v1 = -1e30f;
                    if (!((wwb >> bit) & 1)) v1 = -1e9f;
                    sacc[nt][2+j] = v1; rm1 = fmaxf(rm1, v1);
                }
            }
            rm0 = fmaxf(rm0, __shfl_xor_sync(0xffffffffu, rm0, 1));
            rm0 = fmaxf(rm0, __shfl_xor_sync(0xffffffffu, rm0, 2));
            rm1 = fmaxf(rm1, __shfl_xor_sync(0xffffffffu, rm1, 1));
            rm1 = fmaxf(rm1, __shfl_xor_sync(0xffffffffu, rm1, 2));
            float mn0 = fmaxf(m0, rm0), mn1 = fmaxf(m1, rm1);
            float rs0 = 0.f, rs1 = 0.f;
#pragma unroll
            for (int nt = 0; nt < 8; nt++) {
#pragma unroll
                for (int j = 0; j < 2; j++) {
                    float p0 = __expf(sacc[nt][j]   - mn0); sacc[nt][j]   = p0; rs0 += p0;
                    float p1 = __expf(sacc[nt][2+j] - mn1); sacc[nt][2+j] = p1; rs1 += p1;
                }
            }
            rs0 += __shfl_xor_sync(0xffffffffu, rs0, 1);
            rs0 += __shfl_xor_sync(0xffffffffu, rs0, 2);
            rs1 += __shfl_xor_sync(0xffffffffu, rs1, 1);
            rs1 += __shfl_xor_sync(0xffffffffu, rs1, 2);
            float corr0 = __expf(m0 - mn0), corr1 = __expf(m1 - mn1);
            l0 = l0*corr0 + rs0; l1 = l1*corr1 + rs1;
            m0 = mn0; m1 = mn1;

            // P -> registers (accumulator layout == A-fragment layout)
            unsigned ph0[8], ph1[8];
#pragma unroll
            for (int nt = 0; nt < 8; nt++) {
                ph0[nt] = f2h2(sacc[nt][0], sacc[nt][1]);
                ph1[nt] = f2h2(sacc[nt][2], sacc[nt][3]);
            }

            // rescale O, then GEMM2: O (m16 x n128) += P @ V
#pragma unroll
            for (int nt = 0; nt < 16; nt++) {
                oacc[nt][0] *= corr0; oacc[nt][1] *= corr0;
                oacc[nt][2] *= corr1; oacc[nt][3] *= corr1;
            }
#pragma unroll
            for (int ks2 = 0; ks2 < 4; ks2++) {
                unsigned a0 = ph0[2*ks2],   a1 = ph1[2*ks2];
                unsigned a2 = ph0[2*ks2+1], a3 = ph1[2*ks2+1];
#pragma unroll
                for (int ntp = 0; ntp < 8; ntp++) {
                    unsigned b0, b1, b2, b3;
                    ldm_x4(b0, b1, b2, b3,
                        sptr(&Vc[((ntp*2 + bsel)*8 + brow)*72 + ks2*16 + bcol]));
                    mma16(oacc[ntp*2],     a0, a1, a2, a3, b0, b1);
                    mma16(oacc[ntp*2 + 1], a0, a1, a2, a3, b2, b3);
                }
            }
        }

        float inv0 = 1.f / l0, inv1 = 1.f / l1;
        size_t obase = (size_t)(b*TT + qt*128 + wp*16 + g)*TS + h*EE;
#pragma unroll
        for (int nt = 0; nt < 16; nt++) {
            int col = nt*8 + 2*c;
            *(__half2*)&g_oh[obase + col] =
                __floats2half2_rn(oacc[nt][0]*inv0, oacc[nt][1]*inv0);
            *(__half2*)&g_oh[obase + (size_t)8*TS + col] =
                __floats2half2_rn(oacc[nt][2]*inv1, oacc[nt][3]*inv1);
        }
    }
}

// ---------------------------------------------------------------------------
// Output projection: out = O @ Wu^T + bu. Pipelined K=1024, ldmatrix frags.
// ---------------------------------------------------------------------------
__global__ __launch_bounds__(256, 1) void out_gemm(const float* __restrict__ bu,
                                                   float* __restrict__ out)
{
    extern __shared__ __half smh[];
    __half* As = smh;                // 2 x [128][136]
    __half* Ws = smh + 2*128*136;    // 2 x [64][136]
    const int tid = threadIdx.x, lane = tid & 31, wp = tid >> 5;
    const int g = lane >> 2, c = lane & 3;
    const int arow = (lane & 7) + ((lane & 8) ? 8 : 0);
    const int acol = (lane & 16) ? 8 : 0;
    const int brow = lane & 7;
    const int bcol = (lane & 8) ? 8 : 0;
    const int bsel = (lane >> 4) & 1;
    const int bm = blockIdx.x*128, bn = blockIdx.y*64;

#pragma unroll
    for (int it = 0; it < 8; it++) {
        int id = tid + it*256, r = id >> 4, ch = id & 15;
        cpa16(sptr(&As[r*136 + ch*8]), &g_oh[(size_t)(bm + r)*TS + ch*8]);
    }
#pragma unroll
    for (int it = 0; it < 4; it++) {
        int id = tid + it*256, r = id >> 4, ch = id & 15;
        cpa16(sptr(&Ws[r*136 + ch*8]), &g_wuh[(size_t)(bn + r)*TS + ch*8]);
    }
    CP_COMMIT();

    float acc[8][4];
#pragma unroll
    for (int i = 0; i < 8; i++)
#pragma unroll
        for (int j = 0; j < 4; j++) acc[i][j] = 0.f;

    for (int kt = 0; kt < 8; kt++) {
        const int cur = kt & 1;
        __syncthreads();
        if (kt < 7) {
            const int nb = cur ^ 1;
            int k0 = (kt + 1)*128;
            __half* Ad = As + nb*128*136;
            __half* Wd = Ws + nb*64*136;
#pragma unroll
            for (int it = 0; it < 8; it++) {
                int id = tid + it*256, r = id >> 4, ch = id & 15;
                cpa16(sptr(&Ad[r*136 + ch*8]),
                      &g_oh[(size_t)(bm + r)*TS + k0 + ch*8]);
            }
#pragma unroll
            for (int it = 0; it < 4; it++) {
                int id = tid + it*256, r = id >> 4, ch = id & 15;
                cpa16(sptr(&Wd[r*136 + ch*8]),
                      &g_wuh[(size_t)(bn + r)*TS + k0 + ch*8]);
            }
            CP_COMMIT();
            CP_WAIT1();
        } else {
            CP_WAIT0();
        }
        __syncthreads();

        const __half* Ac = As + cur*128*136;
        const __half* Wc = Ws + cur*64*136;
#pragma unroll
        for (int ks = 0; ks < 8; ks++) {
            unsigned a0, a1, a2, a3;
            ldm_x4(a0, a1, a2, a3,
                   sptr(&Ac[(wp*16 + arow)*136 + ks*16 + acol]));
#pragma unroll
            for (int ntp = 0; ntp < 4; ntp++) {
                unsigned b0, b1, b2, b3;
                ldm_x4(b0, b1, b2, b3,
                       sptr(&Wc[((ntp*2 + bsel)*8 + brow)*136 + ks*16 + bcol]));
                mma16(acc[ntp*2],     a0, a1, a2, a3, b0, b1);
                mma16(acc[ntp*2 + 1], a0, a1, a2, a3, b2, b3);
            }
        }
    }

    const int r0 = bm + wp*16 + g;
#pragma unroll
    for (int nt = 0; nt < 8; nt++) {
        int col = bn + nt*8 + 2*c;
        float b0 = bu[col], b1 = bu[col + 1];
        *(float2*)&out[(size_t)r0*EE + col] =
            make_float2(acc[nt][0] + b0, acc[nt][1] + b1);
        *(float2*)&out[(size_t)(r0+8)*EE + col] =
            make_float2(acc[nt][2] + b0, acc[nt][3] + b1);
    }
}

// ---------------------------------------------------------------------------
extern "C" void kernel_launch(void* const* d_in, const int* in_sizes, int n_in,
                              void* d_out, int out_size)
{
    const float* x    = (const float*)d_in[0];
    const int*   mask = (const int*)  d_in[1];
    const float* Wk   = (const float*)d_in[2];
    const float* Wq   = (const float*)d_in[3];
    const float* Wv   = (const float*)d_in[4];
    const float* Wu   = (const float*)d_in[5];
    const float* bu   = (const float*)d_in[6];
    float* out = (float*)d_out;

    convert_inputs<<<(BB*TT*EE + 255)/256, 256>>>(x, Wq, Wk, Wv, Wu);
    pack_mask<<<(TT*TT/32 + 255)/256, 256>>>(mask);

    const int qkv_smem  = (128*136 + 64*136) * sizeof(__half);               // 52.2 KB
    const int attn_smem = (128*136 + 2*64*136 + 2*128*72) * sizeof(__half);  // 104 KB
    const int outp_smem = (2*128*136 + 2*64*136) * sizeof(__half);           // 104.4 KB
    cudaFuncSetAttribute(qkv_gemm, cudaFuncAttributeMaxDynamicSharedMemorySize, qkv_smem);
    cudaFuncSetAttribute(attn_tc,  cudaFuncAttributeMaxDynamicSharedMemorySize, attn_smem);
    cudaFuncSetAttribute(out_gemm, cudaFuncAttributeMaxDynamicSharedMemorySize, outp_smem);

    dim3 gq(BB*TT/128, TS/64, 3);
    qkv_gemm<<<gq, 256, qkv_smem>>>();

    dim3 ga(4, HH, BB);            // paired q-tiles (qt, 7-qt)
    attn_tc<<<ga, 256, attn_smem>>>();

    dim3 go(BB*TT/128, EE/64);
    out_gemm<<<go, 256, outp_smem>>>(bu, out);
}

// round 7
// speedup vs baseline: 7.2035x; 1.1605x over previous
#include <cuda_runtime.h>
#include <cuda_fp16.h>
#include <math.h>

#define BB 8
#define TT 1024
#define EE 128
#define HH 8
#define TS (HH*EE)   // 1024

// 1/sqrt(128) * log2(e): softmax computed in exp2 domain
#define QSCALE  (0.08838834764831843f * 1.4426950408889634f)
#define NEG_PAD (-1.4426950408889634e9f)   // -1e9 * log2(e)
#define NEG_INF (-1e30f)

// fp16 scratch (allocation-free)
__device__ __align__(16) __half g_xh [BB*TT*EE];
__device__ __align__(16) __half g_wqh[TS*EE];
__device__ __align__(16) __half g_wkh[TS*EE];
__device__ __align__(16) __half g_wvh[TS*EE];
__device__ __align__(16) __half g_wuh[EE*TS];
__device__ __align__(16) __half g_qh [BB*TT*TS];   // pre-scaled by QSCALE
__device__ __align__(16) __half g_kh [BB*TT*TS];
__device__ __align__(16) __half g_vT [BB*HH*EE*TT];  // [b,h,d,t]
__device__ __align__(16) __half g_oh [BB*TT*TS];
__device__ unsigned g_maskp[TT*TT/32];

// ---------------------------------------------------------------------------
// helpers
// ---------------------------------------------------------------------------
__device__ __forceinline__ unsigned sptr(const void* p) {
    return (unsigned)__cvta_generic_to_shared(p);
}
__device__ __forceinline__ void cpa16(unsigned d, const void* g) {
    asm volatile("cp.async.cg.shared.global [%0], [%1], 16;\n" :: "r"(d), "l"(g));
}
#define CP_COMMIT() asm volatile("cp.async.commit_group;\n")
#define CP_WAIT0()  asm volatile("cp.async.wait_group 0;\n")
#define CP_WAIT1()  asm volatile("cp.async.wait_group 1;\n")

__device__ __forceinline__ unsigned ldh2(const __half* p) {
    return *(const unsigned*)p;
}
__device__ __forceinline__ void ldm_x4(unsigned& r0, unsigned& r1,
                                       unsigned& r2, unsigned& r3, unsigned a) {
    asm volatile("ldmatrix.sync.aligned.m8n8.x4.shared.b16 {%0,%1,%2,%3}, [%4];"
        : "=r"(r0), "=r"(r1), "=r"(r2), "=r"(r3) : "r"(a));
}
__device__ __forceinline__ void mma16(float* d, unsigned a0, unsigned a1,
                                      unsigned a2, unsigned a3,
                                      unsigned b0, unsigned b1) {
    asm("mma.sync.aligned.m16n8k16.row.col.f32.f16.f16.f32 "
        "{%0,%1,%2,%3}, {%4,%5,%6,%7}, {%8,%9}, {%0,%1,%2,%3};"
        : "+f"(d[0]), "+f"(d[1]), "+f"(d[2]), "+f"(d[3])
        : "r"(a0), "r"(a1), "r"(a2), "r"(a3), "r"(b0), "r"(b1));
}
__device__ __forceinline__ unsigned f2h2(float lo, float hi) {
    __half2 h = __floats2half2_rn(lo, hi);
    return *(unsigned*)&h;
}

// ---------------------------------------------------------------------------
// one-time conversions
// ---------------------------------------------------------------------------
__global__ void convert_inputs(const float* __restrict__ x,
                               const float* __restrict__ Wq,
                               const float* __restrict__ Wk,
                               const float* __restrict__ Wv,
                               const float* __restrict__ Wu) {
    int i = blockIdx.x * blockDim.x + threadIdx.x;
    if (i < BB*TT*EE) g_xh[i] = __float2half_rn(x[i]);
    if (i < TS*EE) {
        g_wqh[i] = __float2half_rn(Wq[i]);
        g_wkh[i] = __float2half_rn(Wk[i]);
        g_wvh[i] = __float2half_rn(Wv[i]);
        g_wuh[i] = __float2half_rn(Wu[i]);
    }
}

__global__ void pack_mask(const int* __restrict__ mask) {
    int w = blockIdx.x * blockDim.x + threadIdx.x;
    if (w >= TT*TT/32) return;
    const int* src = mask + w*32;
    unsigned bits = 0;
#pragma unroll
    for (int i = 0; i < 32; i++) bits |= (src[i] != 0 ? 1u : 0u) << i;
    g_maskp[w] = bits;
}

// ---------------------------------------------------------------------------
// QKV projection: C = x @ W^T. Block tile 128x64, K=128, 2 CTAs/SM.
// z selects Q/K/V; Q pre-scaled by QSCALE; V written transposed [b,h,d,t].
// ---------------------------------------------------------------------------
__global__ __launch_bounds__(256, 2) void qkv_gemm()
{
    extern __shared__ __half smh[];
    __half* As = smh;            // [128][136]
    __half* Ws = smh + 128*136;  // [64][136]
    const int tid = threadIdx.x, lane = tid & 31, wp = tid >> 5;
    const int g = lane >> 2, c = lane & 3;
    const int brow = lane & 7;
    const int bcol = (lane & 8) ? 8 : 0;
    const int bsel = (lane >> 4) & 1;
    const int bm = blockIdx.x*128, bn = blockIdx.y*64, z = blockIdx.z;
    const __half* W = (z == 0) ? g_wqh : (z == 1) ? g_wkh : g_wvh;

#pragma unroll
    for (int it = 0; it < 8; it++) {
        int id = tid + it*256, r = id >> 4, ch = id & 15;
        cpa16(sptr(&As[r*136 + ch*8]), &g_xh[(size_t)(bm + r)*EE + ch*8]);
    }
#pragma unroll
    for (int it = 0; it < 4; it++) {
        int id = tid + it*256, r = id >> 4, ch = id & 15;
        cpa16(sptr(&Ws[r*136 + ch*8]), &W[(size_t)(bn + r)*EE + ch*8]);
    }
    CP_COMMIT(); CP_WAIT0();
    __syncthreads();

    float acc[8][4];
#pragma unroll
    for (int i = 0; i < 8; i++)
#pragma unroll
        for (int j = 0; j < 4; j++) acc[i][j] = 0.f;

#pragma unroll
    for (int ks = 0; ks < 8; ks++) {
        const __half* pa = &As[(wp*16 + g)*136 + ks*16 + 2*c];
        unsigned a0 = ldh2(pa), a1 = ldh2(pa + 8*136);
        unsigned a2 = ldh2(pa + 8), a3 = ldh2(pa + 8*136 + 8);
#pragma unroll
        for (int ntp = 0; ntp < 4; ntp++) {
            unsigned b0, b1, b2, b3;
            ldm_x4(b0, b1, b2, b3,
                   sptr(&Ws[((ntp*2 + bsel)*8 + brow)*136 + ks*16 + bcol]));
            mma16(acc[ntp*2],     a0, a1, a2, a3, b0, b1);
            mma16(acc[ntp*2 + 1], a0, a1, a2, a3, b2, b3);
        }
    }

    const int r0 = bm + wp*16 + g;
    if (z < 2) {
        __half* dst = (z == 0) ? g_qh : g_kh;
        const float sc = (z == 0) ? QSCALE : 1.0f;
#pragma unroll
        for (int nt = 0; nt < 8; nt++) {
            int col = bn + nt*8 + 2*c;
            *(__half2*)&dst[(size_t)r0*TS + col] =
                __floats2half2_rn(acc[nt][0]*sc, acc[nt][1]*sc);
            *(__half2*)&dst[(size_t)(r0+8)*TS + col] =
                __floats2half2_rn(acc[nt][2]*sc, acc[nt][3]*sc);
        }
    } else {
        int b = r0 >> 10, t = r0 & 1023;
#pragma unroll
        for (int nt = 0; nt < 8; nt++) {
            int col = bn + nt*8 + 2*c;
            int h = col >> 7, d = col & 127;
            __half* vt = &g_vT[(size_t)((b*HH + h)*EE + d)*TT + t];
            vt[0]      = __float2half_rn(acc[nt][0]);
            vt[TT]     = __float2half_rn(acc[nt][1]);
            vt[8]      = __float2half_rn(acc[nt][2]);
            vt[TT + 8] = __float2half_rn(acc[nt][3]);
        }
    }
}

// ---------------------------------------------------------------------------
// Flash attention: fp16 mma, exp2-domain softmax, cp.async double-buffer,
// paired q-tiles, cheap mask-only extension tiles, 2 CTAs/SM.
// ---------------------------------------------------------------------------
__global__ __launch_bounds__(256, 2) void attn_tc()
{
    extern __shared__ __half smh[];
    __half* Qs = smh;                  // [128][136]
    __half* Ks = Qs + 128*136;         // 2 x [64][136]
    __half* Vs = Ks + 2*64*136;        // 2 x [128][72]  (V^T: d rows, t cols)

    const int tid = threadIdx.x, lane = tid & 31, wp = tid >> 5;
    const int g = lane >> 2, c = lane & 3;
    const int h = blockIdx.y, b = blockIdx.z;

    // ldmatrix lane addressing
    const int arow = (lane & 7) + ((lane & 8) ? 8 : 0);
    const int acol = (lane & 16) ? 8 : 0;
    const int brow = lane & 7;
    const int bcol = (lane & 8) ? 8 : 0;
    const int bsel = (lane >> 4) & 1;

    const __half* kg = g_kh + (size_t)(b*TT)*TS + h*EE;
    const __half* vg = g_vT + (size_t)((b*HH + h)*EE)*TT;

    for (int rep = 0; rep < 2; rep++) {
        const int qt = rep ? (7 - blockIdx.x) : blockIdx.x;
        const __half* qg = g_qh + (size_t)(b*TT + qt*128)*TS + h*EE;
        const int qa = qt*128 + wp*16 + g;
        const int qb = qa + 8;

        // static extension predicate: whole causal prefix padding-masked?
        bool need = false;
        if (c == 0) {
#pragma unroll
            for (int rr = 0; rr < 2; rr++) {
                int q = rr ? qb : qa;
                const unsigned* mr = g_maskp + q*32;
                int wlast = q >> 5;
                bool allz = true;
                for (int w = 0; w <= wlast; w++) {
                    unsigned m = mr[w];
                    if (w == wlast) m &= (0xFFFFFFFFu >> (31 - (q & 31)));
                    allz &= (m == 0);
                }
                need |= allz;
            }
        }
        // this barrier also guards smem reuse across reps
        const int kt_last = __syncthreads_or(need) ? (TT/64 - 1) : 2*qt + 1;

        // prologue: Q + K0 + V0
#pragma unroll
        for (int it = 0; it < 8; it++) {
            int id = tid + it*256, r = id >> 4, ch = id & 15;
            cpa16(sptr(&Qs[r*136 + ch*8]), qg + (size_t)r*TS + ch*8);
        }
#pragma unroll
        for (int it = 0; it < 4; it++) {
            int id = tid + it*256, r = id >> 4, ch = id & 15;
            cpa16(sptr(&Ks[r*136 + ch*8]), kg + (size_t)r*TS + ch*8);
        }
#pragma unroll
        for (int it = 0; it < 4; it++) {
            int id = tid + it*256, r = id >> 3, ch = id & 7;
            cpa16(sptr(&Vs[r*72 + ch*8]), vg + (size_t)r*TT + ch*8);
        }
        CP_COMMIT();
        CP_WAIT0();
        __syncthreads();

        float m0 = NEG_INF, m1 = NEG_INF, l0 = 0.f, l1 = 0.f;
        float oacc[16][4];
#pragma unroll
        for (int i = 0; i < 16; i++)
#pragma unroll
            for (int j = 0; j < 4; j++) oacc[i][j] = 0.f;

        const unsigned* mra = g_maskp + qa*32;
        const unsigned* mrb = g_maskp + qb*32;

        for (int kt = 0; kt <= kt_last; kt++) {
            const int cur = kt & 1;
            const bool ext  = (kt > 2*qt + 1);   // fully-future tile
            const bool diag = (kt >= 2*qt);      // causal predicate needed
            __syncthreads();                 // prev compute done before refill
            if (kt + 1 <= kt_last) {
                const int nb = cur ^ 1;
                const bool nk = (kt + 1 <= 2*qt + 1);   // next tile needs K
                __half* Kd = Ks + nb*64*136;
                __half* Vd = Vs + nb*128*72;
                const __half* ksg = kg + (size_t)(kt+1)*64*TS;
                const __half* vsg = vg + (kt+1)*64;
                if (nk) {
#pragma unroll
                    for (int it = 0; it < 4; it++) {
                        int id = tid + it*256, r = id >> 4, ch = id & 15;
                        cpa16(sptr(&Kd[r*136 + ch*8]), ksg + (size_t)r*TS + ch*8);
                    }
                }
#pragma unroll
                for (int it = 0; it < 4; it++) {
                    int id = tid + it*256, r = id >> 3, ch = id & 7;
                    cpa16(sptr(&Vd[r*72 + ch*8]), vsg + (size_t)r*TT + ch*8);
                }
                CP_COMMIT();
                CP_WAIT1();
            } else {
                CP_WAIT0();
            }
            __syncthreads();

            const __half* Kc = Ks + cur*64*136;
            const __half* Vc = Vs + cur*128*72;

            unsigned wa0 = mra[kt*2], wa1 = mra[kt*2 + 1];
            unsigned wb0 = mrb[kt*2], wb1 = mrb[kt*2 + 1];
            float sacc[8][4];

            if (!ext) {
                // ---- GEMM1: S (m16 x n64) = Q @ K^T ----
#pragma unroll
                for (int i = 0; i < 8; i++)
#pragma unroll
                    for (int j = 0; j < 4; j++) sacc[i][j] = 0.f;
#pragma unroll
                for (int ks = 0; ks < 8; ks++) {
                    unsigned q0, q1, q2, q3;
                    ldm_x4(q0, q1, q2, q3,
                           sptr(&Qs[(wp*16 + arow)*136 + ks*16 + acol]));
#pragma unroll
                    for (int ntp = 0; ntp < 4; ntp++) {
                        unsigned b0, b1, b2, b3;
                        ldm_x4(b0, b1, b2, b3,
                            sptr(&Kc[((ntp*2 + bsel)*8 + brow)*136 + ks*16 + bcol]));
                        mma16(sacc[ntp*2],     q0, q1, q2, q3, b0, b1);
                        mma16(sacc[ntp*2 + 1], q0, q1, q2, q3, b2, b3);
                    }
                }

                // ---- softmax (exp2 domain; exact reference mask semantics) ----
                float rm0 = -3e38f, rm1 = -3e38f;
#pragma unroll
                for (int nt = 0; nt < 8; nt++) {
#pragma unroll
                    for (int j = 0; j < 2; j++) {
                        int col = nt*8 + 2*c + j;
                        int kkg = kt*64 + col;
                        int bit = col & 31;
                        unsigned wwa = (col < 32) ? wa0 : wa1;
                        unsigned wwb = (col < 32) ? wb0 : wb1;
                        float v0 = sacc[nt][j];
                        if (diag && kkg > qa) v0 = NEG_INF;     // causal first
                        if (!((wwa >> bit) & 1)) v0 = NEG_PAD;  // padding overwrites
                        sacc[nt][j] = v0; rm0 = fmaxf(rm0, v0);
                        float v1 = sacc[nt][2+j];
                        if (diag && kkg > qb) v1 = NEG_INF;
                        if (!((wwb >> bit) & 1)) v1 = NEG_PAD;
                        sacc[nt][2+j] = v1; rm1 = fmaxf(rm1, v1);
                    }
                }
                rm0 = fmaxf(rm0, __shfl_xor_sync(0xffffffffu, rm0, 1));
                rm0 = fmaxf(rm0, __shfl_xor_sync(0xffffffffu, rm0, 2));
                rm1 = fmaxf(rm1, __shfl_xor_sync(0xffffffffu, rm1, 1));
                rm1 = fmaxf(rm1, __shfl_xor_sync(0xffffffffu, rm1, 2));
                float mn0 = fmaxf(m0, rm0), mn1 = fmaxf(m1, rm1);
                float rs0 = 0.f, rs1 = 0.f;
#pragma unroll
                for (int nt = 0; nt < 8; nt++) {
#pragma unroll
                    for (int j = 0; j < 2; j++) {
                        float p0 = exp2f(sacc[nt][j]   - mn0); sacc[nt][j]   = p0; rs0 += p0;
                        float p1 = exp2f(sacc[nt][2+j] - mn1); sacc[nt][2+j] = p1; rs1 += p1;
                    }
                }
                rs0 += __shfl_xor_sync(0xffffffffu, rs0, 1);
                rs0 += __shfl_xor_sync(0xffffffffu, rs0, 2);
                rs1 += __shfl_xor_sync(0xffffffffu, rs1, 1);
                rs1 += __shfl_xor_sync(0xffffffffu, rs1, 2);
                float corr0 = exp2f(m0 - mn0), corr1 = exp2f(m1 - mn1);
                l0 = l0*corr0 + rs0; l1 = l1*corr1 + rs1;
                m0 = mn0; m1 = mn1;

                // rescale O
#pragma unroll
                for (int nt = 0; nt < 16; nt++) {
                    oacc[nt][0] *= corr0; oacc[nt][1] *= corr0;
                    oacc[nt][2] *= corr1; oacc[nt][3] *= corr1;
                }
            } else {
                // ---- cheap extension tile: S known from mask bits alone ----
                // dead rows (whole causal prefix padded): P = !bit; alive: P = 0.
                // m unchanged, corr == 1.
                bool dead0 = (m0 < -1e8f), dead1 = (m1 < -1e8f);
                bool wdead = __any_sync(0xffffffffu, dead0 || dead1);
                if (!wdead) continue;    // nothing to add; barriers already done
                float rs0 = 0.f, rs1 = 0.f;
#pragma unroll
                for (int nt = 0; nt < 8; nt++) {
#pragma unroll
                    for (int j = 0; j < 2; j++) {
                        int col = nt*8 + 2*c + j;
                        int bit = col & 31;
                        unsigned wwa = (col < 32) ? wa0 : wa1;
                        unsigned wwb = (col < 32) ? wb0 : wb1;
                        float p0 = (dead0 && !((wwa >> bit) & 1)) ? 1.f : 0.f;
                        float p1 = (dead1 && !((wwb >> bit) & 1)) ? 1.f : 0.f;
                        sacc[nt][j] = p0;   rs0 += p0;
                        sacc[nt][2+j] = p1; rs1 += p1;
                    }
                }
                rs0 += __shfl_xor_sync(0xffffffffu, rs0, 1);
                rs0 += __shfl_xor_sync(0xffffffffu, rs0, 2);
                rs1 += __shfl_xor_sync(0xffffffffu, rs1, 1);
                rs1 += __shfl_xor_sync(0xffffffffu, rs1, 2);
                l0 += rs0; l1 += rs1;
            }

            // P -> registers (accumulator layout == A-fragment layout)
            unsigned ph0[8], ph1[8];
#pragma unroll
            for (int nt = 0; nt < 8; nt++) {
                ph0[nt] = f2h2(sacc[nt][0], sacc[nt][1]);
                ph1[nt] = f2h2(sacc[nt][2], sacc[nt][3]);
            }

            // GEMM2: O (m16 x n128) += P @ V
#pragma unroll
            for (int ks2 = 0; ks2 < 4; ks2++) {
                unsigned a0 = ph0[2*ks2],   a1 = ph1[2*ks2];
                unsigned a2 = ph0[2*ks2+1], a3 = ph1[2*ks2+1];
#pragma unroll
                for (int ntp = 0; ntp < 8; ntp++) {
                    unsigned b0, b1, b2, b3;
                    ldm_x4(b0, b1, b2, b3,
                        sptr(&Vc[((ntp*2 + bsel)*8 + brow)*72 + ks2*16 + bcol]));
                    mma16(oacc[ntp*2],     a0, a1, a2, a3, b0, b1);
                    mma16(oacc[ntp*2 + 1], a0, a1, a2, a3, b2, b3);
                }
            }
        }

        float inv0 = 1.f / l0, inv1 = 1.f / l1;
        size_t obase = (size_t)(b*TT + qt*128 + wp*16 + g)*TS + h*EE;
#pragma unroll
        for (int nt = 0; nt < 16; nt++) {
            int col = nt*8 + 2*c;
            *(__half2*)&g_oh[obase + col] =
                __floats2half2_rn(oacc[nt][0]*inv0, oacc[nt][1]*inv0);
            *(__half2*)&g_oh[obase + (size_t)8*TS + col] =
                __floats2half2_rn(oacc[nt][2]*inv1, oacc[nt][3]*inv1);
        }
    }
}

// ---------------------------------------------------------------------------
// Output projection: out = O @ Wu^T + bu. Pipelined K=1024, 2 CTAs/SM.
// ---------------------------------------------------------------------------
__global__ __launch_bounds__(256, 2) void out_gemm(const float* __restrict__ bu,
                                                   float* __restrict__ out)
{
    extern __shared__ __half smh[];
    __half* As = smh;                // 2 x [128][136]
    __half* Ws = smh + 2*128*136;    // 2 x [64][136]
    const int tid = threadIdx.x, lane = tid & 31, wp = tid >> 5;
    const int g = lane >> 2, c = lane & 3;
    const int arow = (lane & 7) + ((lane & 8) ? 8 : 0);
    const int acol = (lane & 16) ? 8 : 0;
    const int brow = lane & 7;
    const int bcol = (lane & 8) ? 8 : 0;
    const int bsel = (lane >> 4) & 1;
    const int bm = blockIdx.x*128, bn = blockIdx.y*64;

#pragma unroll
    for (int it = 0; it < 8; it++) {
        int id = tid + it*256, r = id >> 4, ch = id & 15;
        cpa16(sptr(&As[r*136 + ch*8]), &g_oh[(size_t)(bm + r)*TS + ch*8]);
    }
#pragma unroll
    for (int it = 0; it < 4; it++) {
        int id = tid + it*256, r = id >> 4, ch = id & 15;
        cpa16(sptr(&Ws[r*136 + ch*8]), &g_wuh[(size_t)(bn + r)*TS + ch*8]);
    }
    CP_COMMIT();

    float acc[8][4];
#pragma unroll
    for (int i = 0; i < 8; i++)
#pragma unroll
        for (int j = 0; j < 4; j++) acc[i][j] = 0.f;

    for (int kt = 0; kt < 8; kt++) {
        const int cur = kt & 1;
        __syncthreads();
        if (kt < 7) {
            const int nb = cur ^ 1;
            int k0 = (kt + 1)*128;
            __half* Ad = As + nb*128*136;
            __half* Wd = Ws + nb*64*136;
#pragma unroll
            for (int it = 0; it < 8; it++) {
                int id = tid + it*256, r = id >> 4, ch = id & 15;
                cpa16(sptr(&Ad[r*136 + ch*8]),
                      &g_oh[(size_t)(bm + r)*TS + k0 + ch*8]);
            }
#pragma unroll
            for (int it = 0; it < 4; it++) {
                int id = tid + it*256, r = id >> 4, ch = id & 15;
                cpa16(sptr(&Wd[r*136 + ch*8]),
                      &g_wuh[(size_t)(bn + r)*TS + k0 + ch*8]);
            }
            CP_COMMIT();
            CP_WAIT1();
        } else {
            CP_WAIT0();
        }
        __syncthreads();

        const __half* Ac = As + cur*128*136;
        const __half* Wc = Ws + cur*64*136;
#pragma unroll
        for (int ks = 0; ks < 8; ks++) {
            unsigned a0, a1, a2, a3;
            ldm_x4(a0, a1, a2, a3,
                   sptr(&Ac[(wp*16 + arow)*136 + ks*16 + acol]));
#pragma unroll
            for (int ntp = 0; ntp < 4; ntp++) {
                unsigned b0, b1, b2, b3;
                ldm_x4(b0, b1, b2, b3,
                       sptr(&Wc[((ntp*2 + bsel)*8 + brow)*136 + ks*16 + bcol]));
                mma16(acc[ntp*2],     a0, a1, a2, a3, b0, b1);
                mma16(acc[ntp*2 + 1], a0, a1, a2, a3, b2, b3);
            }
        }
    }

    const int r0 = bm + wp*16 + g;
#pragma unroll
    for (int nt = 0; nt < 8; nt++) {
        int col = bn + nt*8 + 2*c;
        float b0 = bu[col], b1 = bu[col + 1];
        *(float2*)&out[(size_t)r0*EE + col] =
            make_float2(acc[nt][0] + b0, acc[nt][1] + b1);
        *(float2*)&out[(size_t)(r0+8)*EE + col] =
            make_float2(acc[nt][2] + b0, acc[nt][3] + b1);
    }
}

// ---------------------------------------------------------------------------
extern "C" void kernel_launch(void* const* d_in, const int* in_sizes, int n_in,
                              void* d_out, int out_size)
{
    const float* x    = (const float*)d_in[0];
    const int*   mask = (const int*)  d_in[1];
    const float* Wk   = (const float*)d_in[2];
    const float* Wq   = (const float*)d_in[3];
    const float* Wv   = (const float*)d_in[4];
    const float* Wu   = (const float*)d_in[5];
    const float* bu   = (const float*)d_in[6];
    float* out = (float*)d_out;

    convert_inputs<<<(BB*TT*EE + 255)/256, 256>>>(x, Wq, Wk, Wv, Wu);
    pack_mask<<<(TT*TT/32 + 255)/256, 256>>>(mask);

    const int qkv_smem  = (128*136 + 64*136) * sizeof(__half);               // 52.2 KB
    const int attn_smem = (128*136 + 2*64*136 + 2*128*72) * sizeof(__half);  // 104 KB
    const int outp_smem = (2*128*136 + 2*64*136) * sizeof(__half);           // 104.4 KB
    cudaFuncSetAttribute(qkv_gemm, cudaFuncAttributeMaxDynamicSharedMemorySize, qkv_smem);
    cudaFuncSetAttribute(attn_tc,  cudaFuncAttributeMaxDynamicSharedMemorySize, attn_smem);
    cudaFuncSetAttribute(out_gemm, cudaFuncAttributeMaxDynamicSharedMemorySize, outp_smem);

    dim3 gq(BB*TT/128, TS/64, 3);
    qkv_gemm<<<gq, 256, qkv_smem>>>();

    dim3 ga(4, HH, BB);            // paired q-tiles (qt, 7-qt)
    attn_tc<<<ga, 256, attn_smem>>>();

    dim3 go(BB*TT/128, EE/64);
    out_gemm<<<go, 256, outp_smem>>>(bu, out);
}